// round 1
// baseline (speedup 1.0000x reference)
#include <cuda_runtime.h>
#include <cuda_bf16.h>

#define B_  2
#define T_  512
#define E_  768
#define H_  12
#define HD_ 64

// scratch for Q, K, V in [B, T, E] layout (e = head*64 + d)
__device__ float g_qkv[3][B_ * T_ * E_];

// ---------------------------------------------------------------------------
// Kernel 1: QKV projection  out = X @ W^T + b   (X: [1024,768], W: [768,768])
// grid.z selects which of q/k/v. 64x64 tile, BK=16, 256 threads, 4x4 microtile.
// ---------------------------------------------------------------------------
__global__ __launch_bounds__(256) void qkv_gemm(
    const float* __restrict__ X,
    const float* __restrict__ wq, const float* __restrict__ bq,
    const float* __restrict__ wk, const float* __restrict__ bk,
    const float* __restrict__ wv, const float* __restrict__ bv)
{
    const float* W; const float* bias; float* out;
    if (blockIdx.z == 0)      { W = wq; bias = bq; out = g_qkv[0]; }
    else if (blockIdx.z == 1) { W = wk; bias = bk; out = g_qkv[1]; }
    else                      { W = wv; bias = bv; out = g_qkv[2]; }

    __shared__ float Xs[64][17];
    __shared__ float Wsh[64][17];

    const int tid = threadIdx.x;
    const int m0 = blockIdx.y * 64;
    const int n0 = blockIdx.x * 64;
    const int tm = tid >> 4;          // 0..15
    const int tn = tid & 15;          // 0..15
    const int lr = tid >> 2;          // 0..63   (load row)
    const int lc = (tid & 3) << 2;    // 0,4,8,12 (load col, float4)

    float acc[4][4] = {};

    for (int k0 = 0; k0 < E_; k0 += 16) {
        float4 xv  = *(const float4*)&X[(m0 + lr) * E_ + k0 + lc];
        float4 wv4 = *(const float4*)&W[(n0 + lr) * E_ + k0 + lc];
        Xs[lr][lc+0]  = xv.x;  Xs[lr][lc+1]  = xv.y;  Xs[lr][lc+2]  = xv.z;  Xs[lr][lc+3]  = xv.w;
        Wsh[lr][lc+0] = wv4.x; Wsh[lr][lc+1] = wv4.y; Wsh[lr][lc+2] = wv4.z; Wsh[lr][lc+3] = wv4.w;
        __syncthreads();
        #pragma unroll
        for (int k = 0; k < 16; k++) {
            float a[4], bb[4];
            #pragma unroll
            for (int i = 0; i < 4; i++) a[i]  = Xs[tm*4+i][k];
            #pragma unroll
            for (int j = 0; j < 4; j++) bb[j] = Wsh[tn*4+j][k];
            #pragma unroll
            for (int i = 0; i < 4; i++)
                #pragma unroll
                for (int j = 0; j < 4; j++)
                    acc[i][j] += a[i] * bb[j];
        }
        __syncthreads();
    }

    #pragma unroll
    for (int i = 0; i < 4; i++) {
        float4 o;
        o.x = acc[i][0] + bias[n0 + tn*4 + 0];
        o.y = acc[i][1] + bias[n0 + tn*4 + 1];
        o.z = acc[i][2] + bias[n0 + tn*4 + 2];
        o.w = acc[i][3] + bias[n0 + tn*4 + 3];
        *(float4*)&out[(m0 + tm*4 + i) * E_ + n0 + tn*4] = o;
    }
}

// ---------------------------------------------------------------------------
// Kernel 2: fused all-pair scores -> grouped-conv MLP -> weighted V sum.
// grid: (T/64 query blocks, 12 q-heads, 2 batches). 256 threads.
// Per K-tile of 16 keys:
//   scores[l, kh] = Q_g[l,:64] . K[t, kh*64:kh*64+64]   (thread = 4 l x 1 t)
//   w[l,t] = MLP_g(scores / sqrt(E))
//   ctx[l,:] += w[l,t] * V_g[t,:]                        (thread = 4 l x 4 d)
// ---------------------------------------------------------------------------
#define TK 16
#define LT 64
// shared memory layout (in floats)
#define QS_OFF 0                       // 64 * 68
#define KS_OFF 4352                    // 16 * 772
#define VS_OFF 16704                   // 16 * 64
#define WS_OFF 17728                   // 64 * 17
#define WT_OFF 18816                   // 128 (group MLP weights)
#define SMEM_FLOATS 18944

__global__ __launch_bounds__(256, 2) void attn_fused(
    const float* __restrict__ w1, const float* __restrict__ b1,
    const float* __restrict__ w2, const float* __restrict__ b2,
    const float* __restrict__ w3, const float* __restrict__ b3,
    const float* __restrict__ w4, const float* __restrict__ b4,
    float* __restrict__ out)
{
    extern __shared__ float sm[];
    float* Qs  = sm + QS_OFF;
    float* Ks  = sm + KS_OFF;
    float* Vs  = sm + VS_OFF;
    float* Ws  = sm + WS_OFF;
    float* w1s = sm + WT_OFF;   // 96: w1[g*8+o][i], o-major
    float* b1s = w1s + 96;      // 8
    float* w2s = b1s + 8;       // 8
    float* scs = w2s + 8;       // [0]=b2, [1..4]=w3, [5..8]=b3, [9..12]=w4, [13]=b4

    const int b  = blockIdx.z;
    const int g  = blockIdx.y;
    const int l0 = blockIdx.x * LT;
    const int tid = threadIdx.x;
    const int tt = tid & 15;    // key index within tile
    const int lg = tid >> 4;    // query group (owns 4 l's)

    const float inv_scale = 0.03608439182435161f;  // 1/sqrt(768)

    const float* Qp = g_qkv[0];
    const float* Kp = g_qkv[1];
    const float* Vp = g_qkv[2];

    // stage group-g MLP weights
    if (tid < 96) w1s[tid] = w1[g*96 + tid];
    if (tid < 8)  { b1s[tid] = b1[g*8 + tid]; w2s[tid] = w2[g*8 + tid]; }
    if (tid < 4)  {
        scs[1 + tid] = w3[g*4 + tid];
        scs[5 + tid] = b3[g*4 + tid];
        scs[9 + tid] = w4[g*4 + tid];
    }
    if (tid == 0) { scs[0] = b2[g]; scs[13] = b4[g]; }

    // stage Q tile for this head: [64 l][64 d], padded rows (68) for banks
    for (int idx = tid; idx < 64*16; idx += 256) {
        int r = idx >> 4, c = (idx & 15) << 2;
        *(float4*)&Qs[r*68 + c] =
            *(const float4*)&Qp[(b*T_ + l0 + r) * E_ + g*HD_ + c];
    }

    float4 accC[4] = {};  // ctx accumulators: 4 l x 4 d (float4)

    for (int t0 = 0; t0 < T_; t0 += TK) {
        __syncthreads();   // previous phase done reading Ks/Vs/Ws (and Qs visible on iter 0)

        // K tile: 16 keys x full 768 channels (all 12 k-heads), rows padded to 772
        for (int idx = tid; idx < TK * 192; idx += 256) {
            int r = idx / 192, c = (idx % 192) << 2;
            *(float4*)&Ks[r*772 + c] =
                *(const float4*)&Kp[(b*T_ + t0 + r) * E_ + c];
        }
        // V tile: 16 keys x 64 (head g only)
        {
            int r = tid >> 4, c = (tid & 15) << 2;
            *(float4*)&Vs[r*64 + c] =
                *(const float4*)&Vp[(b*T_ + t0 + r) * E_ + g*HD_ + c];
        }
        __syncthreads();

        // ---- scores: acc[li][kh] = q[l] . k[t, kh] ----
        float acc[4][12];
        #pragma unroll
        for (int i = 0; i < 4; i++)
            #pragma unroll
            for (int j = 0; j < 12; j++) acc[i][j] = 0.f;

        #pragma unroll 2
        for (int d = 0; d < HD_; d += 4) {
            float4 q0 = *(const float4*)&Qs[(lg*4+0)*68 + d];
            float4 q1 = *(const float4*)&Qs[(lg*4+1)*68 + d];
            float4 q2 = *(const float4*)&Qs[(lg*4+2)*68 + d];
            float4 q3 = *(const float4*)&Qs[(lg*4+3)*68 + d];
            #pragma unroll
            for (int kh = 0; kh < 12; kh++) {
                float4 kf = *(const float4*)&Ks[tt*772 + kh*64 + d];
                acc[0][kh] += q0.x*kf.x + q0.y*kf.y + q0.z*kf.z + q0.w*kf.w;
                acc[1][kh] += q1.x*kf.x + q1.y*kf.y + q1.z*kf.z + q1.w*kf.w;
                acc[2][kh] += q2.x*kf.x + q2.y*kf.y + q2.z*kf.z + q2.w*kf.w;
                acc[3][kh] += q3.x*kf.x + q3.y*kf.y + q3.z*kf.z + q3.w*kf.w;
            }
        }

        // ---- grouped-conv MLP: 12 -> relu(8) -> 1 -> relu(4) -> 1 ----
        #pragma unroll
        for (int li = 0; li < 4; li++) {
            float s[12];
            #pragma unroll
            for (int kh = 0; kh < 12; kh++) s[kh] = acc[li][kh] * inv_scale;
            float a2 = scs[0];
            #pragma unroll
            for (int o = 0; o < 8; o++) {
                float h = b1s[o];
                #pragma unroll
                for (int i = 0; i < 12; i++) h += w1s[o*12 + i] * s[i];
                a2 += w2s[o] * fmaxf(h, 0.f);
            }
            float w = scs[13];
            #pragma unroll
            for (int j = 0; j < 4; j++)
                w += scs[9+j] * fmaxf(scs[1+j] * a2 + scs[5+j], 0.f);
            Ws[(lg*4 + li)*17 + tt] = w;
        }
        __syncthreads();

        // ---- ctx += Ws[64,16] @ Vs[16,64] ----
        #pragma unroll
        for (int t = 0; t < TK; t++) {
            float4 vv = *(const float4*)&Vs[t*64 + tt*4];
            #pragma unroll
            for (int i = 0; i < 4; i++) {
                float wv = Ws[(lg*4 + i)*17 + t];
                accC[i].x += wv * vv.x;
                accC[i].y += wv * vv.y;
                accC[i].z += wv * vv.z;
                accC[i].w += wv * vv.w;
            }
        }
    }

    #pragma unroll
    for (int i = 0; i < 4; i++)
        *(float4*)&out[(b*T_ + l0 + lg*4 + i) * E_ + g*HD_ + tt*4] = accC[i];
}

// ---------------------------------------------------------------------------
extern "C" void kernel_launch(void* const* d_in, const int* in_sizes, int n_in,
                              void* d_out, int out_size)
{
    const float* x  = (const float*)d_in[0];
    const float* wq = (const float*)d_in[1];
    const float* bq = (const float*)d_in[2];
    const float* wk = (const float*)d_in[3];
    const float* bk = (const float*)d_in[4];
    const float* wv = (const float*)d_in[5];
    const float* bv = (const float*)d_in[6];
    const float* w1 = (const float*)d_in[7];
    const float* b1 = (const float*)d_in[8];
    const float* w2 = (const float*)d_in[9];
    const float* b2 = (const float*)d_in[10];
    const float* w3 = (const float*)d_in[11];
    const float* b3 = (const float*)d_in[12];
    const float* w4 = (const float*)d_in[13];
    const float* b4 = (const float*)d_in[14];
    float* out = (float*)d_out;

    dim3 ggrid(E_ / 64, (B_ * T_) / 64, 3);
    qkv_gemm<<<ggrid, 256>>>(x, wq, bq, wk, bk, wv, bv);

    cudaFuncSetAttribute(attn_fused, cudaFuncAttributeMaxDynamicSharedMemorySize,
                         SMEM_FLOATS * (int)sizeof(float));
    dim3 agrid(T_ / LT, H_, B_);
    attn_fused<<<agrid, 256, SMEM_FLOATS * sizeof(float)>>>(
        w1, b1, w2, b2, w3, b3, w4, b4, out);
}

// round 2
// speedup vs baseline: 3.3410x; 3.3410x over previous
#include <cuda_runtime.h>
#include <cuda_bf16.h>

#define B_  2
#define T_  512
#define E_  768
#define H_  12
#define HD_ 64

// scratch for Q, K, V in [B, T, E] layout (e = head*64 + d)
__device__ float g_qkv[3][B_ * T_ * E_];

__device__ __forceinline__ unsigned f2tf32(float f) {
    unsigned u;
    asm("cvt.rna.tf32.f32 %0, %1;" : "=r"(u) : "f"(f));
    return u;
}

__device__ __forceinline__ void mma_tf32(
    float& d0, float& d1, float& d2, float& d3,
    unsigned a0, unsigned a1, unsigned a2, unsigned a3,
    unsigned b0, unsigned b1)
{
    asm volatile(
        "mma.sync.aligned.m16n8k8.row.col.f32.tf32.tf32.f32 "
        "{%0,%1,%2,%3}, {%4,%5,%6,%7}, {%8,%9}, {%0,%1,%2,%3};"
        : "+f"(d0), "+f"(d1), "+f"(d2), "+f"(d3)
        : "r"(a0), "r"(a1), "r"(a2), "r"(a3), "r"(b0), "r"(b1));
}

// ---------------------------------------------------------------------------
// Kernel 1: QKV projection via tf32 mma.  out = X @ W^T + b
// X: [1024,768], W: [768,768]. Tile 64x64, BK=16, 256 threads (8 warps).
// warp tile: 16m x 32n (mw in 0..3, nw in 0..1).
// ---------------------------------------------------------------------------
__global__ __launch_bounds__(256) void qkv_mma(
    const float* __restrict__ X,
    const float* __restrict__ wq, const float* __restrict__ bq,
    const float* __restrict__ wk, const float* __restrict__ bk,
    const float* __restrict__ wv, const float* __restrict__ bv)
{
    const float* W; const float* bias; float* out;
    if (blockIdx.z == 0)      { W = wq; bias = bq; out = g_qkv[0]; }
    else if (blockIdx.z == 1) { W = wk; bias = bk; out = g_qkv[1]; }
    else                      { W = wv; bias = bv; out = g_qkv[2]; }

    __shared__ float Xs[64 * 20];
    __shared__ float Wsh[64 * 20];
    const unsigned* Xu = (const unsigned*)Xs;
    const unsigned* Wu = (const unsigned*)Wsh;

    const int tid  = threadIdx.x;
    const int lane = tid & 31;
    const int warp = tid >> 5;
    const int gid  = lane >> 2;   // 0..7
    const int tig  = lane & 3;    // 0..3
    const int mw   = warp & 3;    // m block (16 rows)
    const int nw   = warp >> 2;   // n half (32 cols)

    const int m0 = blockIdx.y * 64;
    const int n0 = blockIdx.x * 64;

    const int lr = tid >> 2;          // 0..63 staging row
    const int lc = (tid & 3) << 2;    // 0,4,8,12

    float acc[4][4];
    #pragma unroll
    for (int nb = 0; nb < 4; nb++)
        #pragma unroll
        for (int i = 0; i < 4; i++) acc[nb][i] = 0.f;

    for (int k0 = 0; k0 < E_; k0 += 16) {
        float4 xv = *(const float4*)&X[(m0 + lr) * E_ + k0 + lc];
        float4 wv4 = *(const float4*)&W[(n0 + lr) * E_ + k0 + lc];
        float4 xc, wc;
        xc.x = __uint_as_float(f2tf32(xv.x));  xc.y = __uint_as_float(f2tf32(xv.y));
        xc.z = __uint_as_float(f2tf32(xv.z));  xc.w = __uint_as_float(f2tf32(xv.w));
        wc.x = __uint_as_float(f2tf32(wv4.x)); wc.y = __uint_as_float(f2tf32(wv4.y));
        wc.z = __uint_as_float(f2tf32(wv4.z)); wc.w = __uint_as_float(f2tf32(wv4.w));
        __syncthreads();
        *(float4*)&Xs[lr * 20 + lc]  = xc;
        *(float4*)&Wsh[lr * 20 + lc] = wc;
        __syncthreads();

        #pragma unroll
        for (int ks = 0; ks < 2; ks++) {
            const int arow = mw * 16 + gid;
            unsigned a0 = Xu[arow * 20 + ks * 8 + tig];
            unsigned a1 = Xu[(arow + 8) * 20 + ks * 8 + tig];
            unsigned a2 = Xu[arow * 20 + ks * 8 + tig + 4];
            unsigned a3 = Xu[(arow + 8) * 20 + ks * 8 + tig + 4];
            #pragma unroll
            for (int nb = 0; nb < 4; nb++) {
                const int brow = nw * 32 + nb * 8 + gid;
                unsigned b0 = Wu[brow * 20 + ks * 8 + tig];
                unsigned b1 = Wu[brow * 20 + ks * 8 + tig + 4];
                mma_tf32(acc[nb][0], acc[nb][1], acc[nb][2], acc[nb][3],
                         a0, a1, a2, a3, b0, b1);
            }
        }
    }

    // epilogue: add bias, store float2 pairs
    #pragma unroll
    for (int nb = 0; nb < 4; nb++) {
        const int c = n0 + nw * 32 + nb * 8 + 2 * tig;
        const float bz0 = bias[c], bz1 = bias[c + 1];
        const int r0 = m0 + mw * 16 + gid;
        float2 o0 = make_float2(acc[nb][0] + bz0, acc[nb][1] + bz1);
        float2 o1 = make_float2(acc[nb][2] + bz0, acc[nb][3] + bz1);
        *(float2*)&out[r0 * E_ + c]       = o0;
        *(float2*)&out[(r0 + 8) * E_ + c] = o1;
    }
}

// ---------------------------------------------------------------------------
// Kernel 2: fused scores(mma.tf32) -> grouped-conv MLP (regs) -> weighted V.
// grid: (T/32, 12 q-heads, 2 batches). 128 threads (4 warps).
// warp tile: 16 l x 8 t, all 12 k-heads. MLP hidden accumulated incrementally.
// ---------------------------------------------------------------------------
#define TK 16
#define LT 32
// shared layout (floats)
#define QS_OFF 0                        // 32 * 68   = 2176
#define KS_OFF 2176                     // 16 * 772  = 12352
#define VS_OFF 14528                    // 16 * 64   = 1024
#define WS_OFF 15552                    // 32 * 18   = 576
#define WT_OFF 16128                    // 128
#define SMEM_FLOATS 16256

__global__ __launch_bounds__(128, 3) void attn_fused(
    const float* __restrict__ w1, const float* __restrict__ b1,
    const float* __restrict__ w2, const float* __restrict__ b2,
    const float* __restrict__ w3, const float* __restrict__ b3,
    const float* __restrict__ w4, const float* __restrict__ b4,
    float* __restrict__ out)
{
    extern __shared__ float sm[];
    float* Qs  = sm + QS_OFF;
    float* Ks  = sm + KS_OFF;
    float* Vs  = sm + VS_OFF;
    float* Ws  = sm + WS_OFF;
    float* w1s = sm + WT_OFF;   // 96 (pre-scaled by 1/sqrt(E))
    float* b1s = w1s + 96;      // 8
    float* w2s = b1s + 8;       // 8
    float* scs = w2s + 8;       // [0]=b2, [1..4]=w3, [5..8]=b3, [9..12]=w4, [13]=b4
    const unsigned* Qu = (const unsigned*)Qs;
    const unsigned* Ku = (const unsigned*)Ks;

    const int b   = blockIdx.z;
    const int g   = blockIdx.y;
    const int l0  = blockIdx.x * LT;
    const int tid = threadIdx.x;
    const int lane = tid & 31;
    const int warp = tid >> 5;
    const int gid  = lane >> 2;   // 0..7
    const int tig  = lane & 3;    // 0..3
    const int lb   = warp >> 1;   // l block (16 rows): 0..1
    const int tb   = warp & 1;    // t block (8 keys):  0..1
    const int tt = tid & 15;      // ctx: d chunk
    const int lg = tid >> 4;      // ctx: l group (4 rows)

    const float inv_scale = 0.03608439182435161f;  // 1/sqrt(768)

    const float* Qp = g_qkv[0];
    const float* Kp = g_qkv[1];
    const float* Vp = g_qkv[2];

    // stage group-g MLP weights (scale folded into w1)
    if (tid < 96) w1s[tid] = w1[g * 96 + tid] * inv_scale;
    if (tid < 8)  { b1s[tid] = b1[g * 8 + tid]; w2s[tid] = w2[g * 8 + tid]; }
    if (tid < 4)  {
        scs[1 + tid] = w3[g * 4 + tid];
        scs[5 + tid] = b3[g * 4 + tid];
        scs[9 + tid] = w4[g * 4 + tid];
    }
    if (tid == 0) { scs[0] = b2[g]; scs[13] = b4[g]; }

    // stage Q tile [32 l][64 d] as tf32 bits, row stride 68
    #pragma unroll
    for (int it = 0; it < 4; it++) {
        int idx = tid + it * 128;
        int r = idx >> 4, c = (idx & 15) << 2;
        float4 qv = *(const float4*)&Qp[(b * T_ + l0 + r) * E_ + g * HD_ + c];
        float4 qc;
        qc.x = __uint_as_float(f2tf32(qv.x)); qc.y = __uint_as_float(f2tf32(qv.y));
        qc.z = __uint_as_float(f2tf32(qv.z)); qc.w = __uint_as_float(f2tf32(qv.w));
        *(float4*)&Qs[r * 68 + c] = qc;
    }

    float4 accC[4] = {};  // ctx accumulators: 4 l x float4 d

    for (int t0 = 0; t0 < T_; t0 += TK) {
        __syncthreads();   // prior phase done with Ks/Vs/Ws (covers Qs on iter 0)

        // K tile: 16 keys x 768 channels, tf32 bits, row stride 772
        #pragma unroll
        for (int it = 0; it < 24; it++) {
            int idx = tid + it * 128;
            int r = idx / 192, c = (idx % 192) << 2;
            float4 kv = *(const float4*)&Kp[(b * T_ + t0 + r) * E_ + c];
            float4 kc;
            kc.x = __uint_as_float(f2tf32(kv.x)); kc.y = __uint_as_float(f2tf32(kv.y));
            kc.z = __uint_as_float(f2tf32(kv.z)); kc.w = __uint_as_float(f2tf32(kv.w));
            *(float4*)&Ks[r * 772 + c] = kc;
        }
        // V tile: 16 keys x 64 (head g), fp32
        #pragma unroll
        for (int it = 0; it < 2; it++) {
            int idx = tid + it * 128;
            int r = idx >> 4, c = (idx & 15) << 2;
            *(float4*)&Vs[r * 64 + c] =
                *(const float4*)&Vp[(b * T_ + t0 + r) * E_ + g * HD_ + c];
        }
        __syncthreads();

        // hoist A fragments (Q rows lb*16+gid, +8) for all 8 k-steps
        unsigned a[8][4];
        {
            const int r0 = (lb * 16 + gid) * 68;
            const int r1 = r0 + 8 * 68;
            #pragma unroll
            for (int ks = 0; ks < 8; ks++) {
                a[ks][0] = Qu[r0 + ks * 8 + tig];
                a[ks][1] = Qu[r1 + ks * 8 + tig];
                a[ks][2] = Qu[r0 + ks * 8 + tig + 4];
                a[ks][3] = Qu[r1 + ks * 8 + tig + 4];
            }
        }

        // MLP hidden accumulators for 4 points (r0,t0)(r0,t1)(r1,t0)(r1,t1)
        float h0[8], h1[8], h2[8], h3[8];
        #pragma unroll
        for (int o = 0; o < 8; o++) { h0[o] = b1s[o]; h1[o] = b1s[o]; h2[o] = b1s[o]; h3[o] = b1s[o]; }

        const int brow = (tb * 8 + gid) * 772;
        #pragma unroll
        for (int kh = 0; kh < 12; kh++) {
            float d0 = 0.f, d1 = 0.f, d2 = 0.f, d3 = 0.f;
            const int koff = brow + kh * 64;
            #pragma unroll
            for (int ks = 0; ks < 8; ks++) {
                unsigned b0 = Ku[koff + ks * 8 + tig];
                unsigned b1v = Ku[koff + ks * 8 + tig + 4];
                mma_tf32(d0, d1, d2, d3, a[ks][0], a[ks][1], a[ks][2], a[ks][3], b0, b1v);
            }
            #pragma unroll
            for (int o = 0; o < 8; o++) {
                float w = w1s[o * 12 + kh];
                h0[o] = fmaf(w, d0, h0[o]);
                h1[o] = fmaf(w, d1, h1[o]);
                h2[o] = fmaf(w, d2, h2[o]);
                h3[o] = fmaf(w, d3, h3[o]);
            }
        }

        // MLP tail per point: relu -> w2 dot -> relu(4) -> w4 dot
        float wout[4];
        {
            float* hp[4] = { h0, h1, h2, h3 };
            #pragma unroll
            for (int p = 0; p < 4; p++) {
                float a2 = scs[0];
                #pragma unroll
                for (int o = 0; o < 8; o++)
                    a2 = fmaf(w2s[o], fmaxf(hp[p][o], 0.f), a2);
                float w = scs[13];
                #pragma unroll
                for (int j = 0; j < 4; j++)
                    w = fmaf(scs[9 + j], fmaxf(fmaf(scs[1 + j], a2, scs[5 + j]), 0.f), w);
                wout[p] = w;
            }
        }
        {
            const int r0 = lb * 16 + gid;
            const int tcol = tb * 8 + 2 * tig;
            *(float2*)&Ws[r0 * 18 + tcol]       = make_float2(wout[0], wout[1]);
            *(float2*)&Ws[(r0 + 8) * 18 + tcol] = make_float2(wout[2], wout[3]);
        }
        __syncthreads();

        // ctx += Ws[32,16] @ Vs[16,64]
        #pragma unroll
        for (int t = 0; t < TK; t++) {
            float4 vv = *(const float4*)&Vs[t * 64 + tt * 4];
            #pragma unroll
            for (int i = 0; i < 4; i++) {
                float wv = Ws[(lg * 4 + i) * 18 + t];
                accC[i].x = fmaf(wv, vv.x, accC[i].x);
                accC[i].y = fmaf(wv, vv.y, accC[i].y);
                accC[i].z = fmaf(wv, vv.z, accC[i].z);
                accC[i].w = fmaf(wv, vv.w, accC[i].w);
            }
        }
    }

    #pragma unroll
    for (int i = 0; i < 4; i++)
        *(float4*)&out[(b * T_ + l0 + lg * 4 + i) * E_ + g * HD_ + tt * 4] = accC[i];
}

// ---------------------------------------------------------------------------
extern "C" void kernel_launch(void* const* d_in, const int* in_sizes, int n_in,
                              void* d_out, int out_size)
{
    const float* x  = (const float*)d_in[0];
    const float* wq = (const float*)d_in[1];
    const float* bq = (const float*)d_in[2];
    const float* wk = (const float*)d_in[3];
    const float* bk = (const float*)d_in[4];
    const float* wv = (const float*)d_in[5];
    const float* bv = (const float*)d_in[6];
    const float* w1 = (const float*)d_in[7];
    const float* b1 = (const float*)d_in[8];
    const float* w2 = (const float*)d_in[9];
    const float* b2 = (const float*)d_in[10];
    const float* w3 = (const float*)d_in[11];
    const float* b3 = (const float*)d_in[12];
    const float* w4 = (const float*)d_in[13];
    const float* b4 = (const float*)d_in[14];
    float* out = (float*)d_out;

    dim3 ggrid(E_ / 64, (B_ * T_) / 64, 3);
    qkv_mma<<<ggrid, 256>>>(x, wq, bq, wk, bk, wv, bv);

    cudaFuncSetAttribute(attn_fused, cudaFuncAttributeMaxDynamicSharedMemorySize,
                         SMEM_FLOATS * (int)sizeof(float));
    dim3 agrid(T_ / LT, H_, B_);
    attn_fused<<<agrid, 128, SMEM_FLOATS * sizeof(float)>>>(
        w1, b1, w2, b2, w3, b3, w4, b4, out);
}

// round 3
// speedup vs baseline: 3.6163x; 1.0824x over previous
#include <cuda_runtime.h>
#include <cuda_bf16.h>

#define B_  2
#define T_  512
#define E_  768
#define H_  12
#define HD_ 64

// scratch for Q, K, V in [B, T, E] layout, values pre-rounded to tf32 (rna)
__device__ float g_qkv[3][B_ * T_ * E_];

__device__ __forceinline__ unsigned f2tf32(float f) {
    unsigned u;
    asm("cvt.rna.tf32.f32 %0, %1;" : "=r"(u) : "f"(f));
    return u;
}

__device__ __forceinline__ void mma_tf32(
    float& d0, float& d1, float& d2, float& d3,
    unsigned a0, unsigned a1, unsigned a2, unsigned a3,
    unsigned b0, unsigned b1)
{
    asm volatile(
        "mma.sync.aligned.m16n8k8.row.col.f32.tf32.tf32.f32 "
        "{%0,%1,%2,%3}, {%4,%5,%6,%7}, {%8,%9}, {%0,%1,%2,%3};"
        : "+f"(d0), "+f"(d1), "+f"(d2), "+f"(d3)
        : "r"(a0), "r"(a1), "r"(a2), "r"(a3), "r"(b0), "r"(b1));
}

__device__ __forceinline__ unsigned smem_u32(const void* p) {
    return (unsigned)__cvta_generic_to_shared(p);
}

__device__ __forceinline__ void cp_async16(unsigned s, const void* g) {
    asm volatile("cp.async.cg.shared.global [%0], [%1], 16;" :: "r"(s), "l"(g));
}
__device__ __forceinline__ void cp_commit() {
    asm volatile("cp.async.commit_group;");
}
__device__ __forceinline__ void cp_wait_all() {
    asm volatile("cp.async.wait_group 0;");
}

// ---------------------------------------------------------------------------
// Kernel 1: QKV projection via tf32 mma.  out = round_tf32(X @ W^T + b)
// Tile 64x64, BK=32, 256 threads (8 warps), warp tile 16m x 32n.
// ---------------------------------------------------------------------------
__global__ __launch_bounds__(256) void qkv_mma(
    const float* __restrict__ X,
    const float* __restrict__ wq, const float* __restrict__ bq,
    const float* __restrict__ wk, const float* __restrict__ bk,
    const float* __restrict__ wv, const float* __restrict__ bv)
{
    const float* W; const float* bias; float* out;
    if (blockIdx.z == 0)      { W = wq; bias = bq; out = g_qkv[0]; }
    else if (blockIdx.z == 1) { W = wk; bias = bk; out = g_qkv[1]; }
    else                      { W = wv; bias = bv; out = g_qkv[2]; }

    __shared__ float Xs[64 * 36];
    __shared__ float Wsh[64 * 36];
    const unsigned* Xu = (const unsigned*)Xs;
    const unsigned* Wu = (const unsigned*)Wsh;

    const int tid  = threadIdx.x;
    const int lane = tid & 31;
    const int warp = tid >> 5;
    const int gid  = lane >> 2;
    const int tig  = lane & 3;
    const int mw   = warp & 3;
    const int nw   = warp >> 2;

    const int m0 = blockIdx.y * 64;
    const int n0 = blockIdx.x * 64;

    const int lr = tid >> 2;
    const int lc = (tid & 3) << 2;

    float acc[4][4];
    #pragma unroll
    for (int nb = 0; nb < 4; nb++)
        #pragma unroll
        for (int i = 0; i < 4; i++) acc[nb][i] = 0.f;

    for (int k0 = 0; k0 < E_; k0 += 32) {
        float4 xv[2], wv4[2];
        #pragma unroll
        for (int h = 0; h < 2; h++) {
            xv[h]  = *(const float4*)&X[(m0 + lr) * E_ + k0 + lc + h * 16];
            wv4[h] = *(const float4*)&W[(n0 + lr) * E_ + k0 + lc + h * 16];
        }
        __syncthreads();
        #pragma unroll
        for (int h = 0; h < 2; h++) {
            float4 xc, wc;
            xc.x = __uint_as_float(f2tf32(xv[h].x));  xc.y = __uint_as_float(f2tf32(xv[h].y));
            xc.z = __uint_as_float(f2tf32(xv[h].z));  xc.w = __uint_as_float(f2tf32(xv[h].w));
            wc.x = __uint_as_float(f2tf32(wv4[h].x)); wc.y = __uint_as_float(f2tf32(wv4[h].y));
            wc.z = __uint_as_float(f2tf32(wv4[h].z)); wc.w = __uint_as_float(f2tf32(wv4[h].w));
            *(float4*)&Xs[lr * 36 + lc + h * 16]  = xc;
            *(float4*)&Wsh[lr * 36 + lc + h * 16] = wc;
        }
        __syncthreads();

        #pragma unroll
        for (int ks = 0; ks < 4; ks++) {
            const int arow = mw * 16 + gid;
            unsigned a0 = Xu[arow * 36 + ks * 8 + tig];
            unsigned a1 = Xu[(arow + 8) * 36 + ks * 8 + tig];
            unsigned a2 = Xu[arow * 36 + ks * 8 + tig + 4];
            unsigned a3 = Xu[(arow + 8) * 36 + ks * 8 + tig + 4];
            #pragma unroll
            for (int nb = 0; nb < 4; nb++) {
                const int brow = nw * 32 + nb * 8 + gid;
                unsigned b0 = Wu[brow * 36 + ks * 8 + tig];
                unsigned b1 = Wu[brow * 36 + ks * 8 + tig + 4];
                mma_tf32(acc[nb][0], acc[nb][1], acc[nb][2], acc[nb][3],
                         a0, a1, a2, a3, b0, b1);
            }
        }
    }

    // epilogue: add bias, round to tf32, store
    #pragma unroll
    for (int nb = 0; nb < 4; nb++) {
        const int c = n0 + nw * 32 + nb * 8 + 2 * tig;
        const float bz0 = bias[c], bz1 = bias[c + 1];
        const int r0 = m0 + mw * 16 + gid;
        float2 o0, o1;
        o0.x = __uint_as_float(f2tf32(acc[nb][0] + bz0));
        o0.y = __uint_as_float(f2tf32(acc[nb][1] + bz1));
        o1.x = __uint_as_float(f2tf32(acc[nb][2] + bz0));
        o1.y = __uint_as_float(f2tf32(acc[nb][3] + bz1));
        *(float2*)&out[r0 * E_ + c]       = o0;
        *(float2*)&out[(r0 + 8) * E_ + c] = o1;
    }
}

// ---------------------------------------------------------------------------
// Kernel 2: fused scores(mma) -> MLP(regs) -> ctx(mma).
// grid: (T/32, 12 q-heads, 2 batches). 128 threads (4 warps), 4 CTAs/SM.
// Q fragments live in registers (loop-invariant). K/V staged via cp.async.
// ---------------------------------------------------------------------------
#define TK 16
#define LT 32
// shared layout (floats)
#define KS_OFF 0                        // 16 * 772 = 12352
#define VS_OFF 12352                    // 16 * 68  = 1088
#define WS_OFF 13440                    // 32 * 20  = 640
#define WT_OFF 14080                    // 128
#define SMEM_FLOATS 14208               // 56832 bytes

__global__ __launch_bounds__(128, 4) void attn_fused(
    const float* __restrict__ w1, const float* __restrict__ b1,
    const float* __restrict__ w2, const float* __restrict__ b2,
    const float* __restrict__ w3, const float* __restrict__ b3,
    const float* __restrict__ w4, const float* __restrict__ b4,
    float* __restrict__ out)
{
    extern __shared__ float sm[];
    float* Ks  = sm + KS_OFF;
    float* Vs  = sm + VS_OFF;
    float* Ws  = sm + WS_OFF;
    float* w1s = sm + WT_OFF;   // 96 (pre-scaled by 1/sqrt(E))
    float* b1s = w1s + 96;      // 8
    float* w2s = b1s + 8;       // 8
    float* scs = w2s + 8;       // [0]=b2, [1..4]=w3, [5..8]=b3, [9..12]=w4, [13]=b4
    const unsigned* Ku  = (const unsigned*)Ks;
    const unsigned* Vu  = (const unsigned*)Vs;
    const unsigned* Wsu = (const unsigned*)Ws;

    const int b   = blockIdx.z;
    const int g   = blockIdx.y;
    const int l0  = blockIdx.x * LT;
    const int tid = threadIdx.x;
    const int lane = tid & 31;
    const int warp = tid >> 5;
    const int gid  = lane >> 2;   // 0..7
    const int tig  = lane & 3;    // 0..3
    const int lb   = warp >> 1;   // l block (16 rows)
    const int tb   = warp & 1;    // t block (8 keys)

    const float inv_scale = 0.03608439182435161f;  // 1/sqrt(768)

    const float* Qp = g_qkv[0];
    const float* Kp = g_qkv[1];
    const float* Vp = g_qkv[2];

    // stage group-g MLP weights (scale folded into w1)
    if (tid < 96) w1s[tid] = w1[g * 96 + tid] * inv_scale;
    if (tid < 8)  { b1s[tid] = b1[g * 8 + tid]; w2s[tid] = w2[g * 8 + tid]; }
    if (tid < 4)  {
        scs[1 + tid] = w3[g * 4 + tid];
        scs[5 + tid] = b3[g * 4 + tid];
        scs[9 + tid] = w4[g * 4 + tid];
    }
    if (tid == 0) { scs[0] = b2[g]; scs[13] = b4[g]; }

    // Q A-fragments in registers (loop-invariant across key tiles)
    unsigned a[8][4];
    {
        const float* qb = Qp + (size_t)(b * T_ + l0 + lb * 16 + gid) * E_ + g * HD_;
        #pragma unroll
        for (int ks = 0; ks < 8; ks++) {
            a[ks][0] = __float_as_uint(qb[ks * 8 + tig]);
            a[ks][1] = __float_as_uint(qb[8 * E_ + ks * 8 + tig]);
            a[ks][2] = __float_as_uint(qb[ks * 8 + tig + 4]);
            a[ks][3] = __float_as_uint(qb[8 * E_ + ks * 8 + tig + 4]);
        }
    }

    // cp.async staging helpers
    const int tr = tid >> 3;          // 0..15 (row)
    const int tc = tid & 7;           // 0..7  (col group)
    const unsigned ks_smem = smem_u32(Ks);
    const unsigned vs_smem = smem_u32(Vs);

    // stage tile 0
    {
        const float* kg = Kp + (size_t)(b * T_ + tr) * E_;
        #pragma unroll
        for (int j = 0; j < 24; j++)
            cp_async16(ks_smem + (unsigned)(tr * 772 + j * 32 + tc * 4) * 4,
                       kg + j * 32 + tc * 4);
        const float* vg = Vp + (size_t)(b * T_ + tr) * E_ + g * HD_;
        #pragma unroll
        for (int j = 0; j < 2; j++)
            cp_async16(vs_smem + (unsigned)(tr * 68 + j * 32 + tc * 4) * 4,
                       vg + j * 32 + tc * 4);
        cp_commit();
        cp_wait_all();
    }
    __syncthreads();

    float cacc[4][4];
    #pragma unroll
    for (int nb = 0; nb < 4; nb++)
        #pragma unroll
        for (int i = 0; i < 4; i++) cacc[nb][i] = 0.f;

    for (int t0 = 0; t0 < T_; t0 += TK) {
        const bool more = (t0 + TK) < T_;

        // ---- scores (mma) fused into MLP hidden accumulation ----
        float h0[8], h1[8], h2[8], h3[8];
        #pragma unroll
        for (int o = 0; o < 8; o++) {
            float bz = b1s[o];
            h0[o] = bz; h1[o] = bz; h2[o] = bz; h3[o] = bz;
        }

        const int brow = (tb * 8 + gid) * 772;
        #pragma unroll
        for (int kh = 0; kh < 12; kh++) {
            float d0 = 0.f, d1 = 0.f, d2 = 0.f, d3 = 0.f;
            const int koff = brow + kh * 64;
            #pragma unroll
            for (int ks = 0; ks < 8; ks++) {
                unsigned b0v = Ku[koff + ks * 8 + tig];
                unsigned b1v = Ku[koff + ks * 8 + tig + 4];
                mma_tf32(d0, d1, d2, d3, a[ks][0], a[ks][1], a[ks][2], a[ks][3], b0v, b1v);
            }
            #pragma unroll
            for (int o = 0; o < 8; o++) {
                float w = w1s[o * 12 + kh];
                h0[o] = fmaf(w, d0, h0[o]);
                h1[o] = fmaf(w, d1, h1[o]);
                h2[o] = fmaf(w, d2, h2[o]);
                h3[o] = fmaf(w, d3, h3[o]);
            }
        }

        // ---- MLP tail: relu -> w2 -> relu(4) -> w4 ----
        float wout[4];
        {
            float* hp[4] = { h0, h1, h2, h3 };
            #pragma unroll
            for (int p = 0; p < 4; p++) {
                float a2 = scs[0];
                #pragma unroll
                for (int o = 0; o < 8; o++)
                    a2 = fmaf(w2s[o], fmaxf(hp[p][o], 0.f), a2);
                float w = scs[13];
                #pragma unroll
                for (int j = 0; j < 4; j++)
                    w = fmaf(scs[9 + j], fmaxf(fmaf(scs[1 + j], a2, scs[5 + j]), 0.f), w);
                wout[p] = __uint_as_float(f2tf32(w));
            }
        }
        {
            const int r0 = lb * 16 + gid;
            const int tcol = tb * 8 + 2 * tig;
            *(float2*)&Ws[r0 * 20 + tcol]       = make_float2(wout[0], wout[1]);
            *(float2*)&Ws[(r0 + 8) * 20 + tcol] = make_float2(wout[2], wout[3]);
        }
        __syncthreads();   // Ws visible; all warps done reading Ks

        // prefetch next K tile (overlaps ctx mma; ctx never reads Ks)
        if (more) {
            const float* kg = Kp + (size_t)(b * T_ + t0 + TK + tr) * E_;
            #pragma unroll
            for (int j = 0; j < 24; j++)
                cp_async16(ks_smem + (unsigned)(tr * 772 + j * 32 + tc * 4) * 4,
                           kg + j * 32 + tc * 4);
            cp_commit();
        }

        // ---- ctx (mma): cacc += Ws[32,16] @ Vs[16,64] ----
        #pragma unroll
        for (int ks = 0; ks < 2; ks++) {
            const int wr = (lb * 16 + gid) * 20 + ks * 8 + tig;
            unsigned wa0 = Wsu[wr];
            unsigned wa1 = Wsu[wr + 8 * 20];
            unsigned wa2 = Wsu[wr + 4];
            unsigned wa3 = Wsu[wr + 8 * 20 + 4];
            #pragma unroll
            for (int nb = 0; nb < 4; nb++) {
                const int d = (tb * 4 + nb) * 8 + gid;
                unsigned b0v = Vu[(ks * 8 + tig) * 68 + d];
                unsigned b1v = Vu[(ks * 8 + tig + 4) * 68 + d];
                mma_tf32(cacc[nb][0], cacc[nb][1], cacc[nb][2], cacc[nb][3],
                         wa0, wa1, wa2, wa3, b0v, b1v);
            }
        }
        __syncthreads();   // ctx done reading Vs & Ws

        if (more) {
            const float* vg = Vp + (size_t)(b * T_ + t0 + TK + tr) * E_ + g * HD_;
            #pragma unroll
            for (int j = 0; j < 2; j++)
                cp_async16(vs_smem + (unsigned)(tr * 68 + j * 32 + tc * 4) * 4,
                           vg + j * 32 + tc * 4);
            cp_commit();
            cp_wait_all();
            __syncthreads();
        }
    }

    // ---- store ctx ----
    #pragma unroll
    for (int nb = 0; nb < 4; nb++) {
        const int row0 = b * T_ + l0 + lb * 16 + gid;
        const int col  = g * HD_ + (tb * 4 + nb) * 8 + 2 * tig;
        *(float2*)&out[(size_t)row0 * E_ + col] = make_float2(cacc[nb][0], cacc[nb][1]);
        *(float2*)&out[(size_t)(row0 + 8) * E_ + col] = make_float2(cacc[nb][2], cacc[nb][3]);
    }
}

// ---------------------------------------------------------------------------
extern "C" void kernel_launch(void* const* d_in, const int* in_sizes, int n_in,
                              void* d_out, int out_size)
{
    const float* x  = (const float*)d_in[0];
    const float* wq = (const float*)d_in[1];
    const float* bq = (const float*)d_in[2];
    const float* wk = (const float*)d_in[3];
    const float* bk = (const float*)d_in[4];
    const float* wv = (const float*)d_in[5];
    const float* bv = (const float*)d_in[6];
    const float* w1 = (const float*)d_in[7];
    const float* b1 = (const float*)d_in[8];
    const float* w2 = (const float*)d_in[9];
    const float* b2 = (const float*)d_in[10];
    const float* w3 = (const float*)d_in[11];
    const float* b3 = (const float*)d_in[12];
    const float* w4 = (const float*)d_in[13];
    const float* b4 = (const float*)d_in[14];
    float* out = (float*)d_out;

    dim3 ggrid(E_ / 64, (B_ * T_) / 64, 3);
    qkv_mma<<<ggrid, 256>>>(x, wq, bq, wk, bk, wv, bv);

    cudaFuncSetAttribute(attn_fused, cudaFuncAttributeMaxDynamicSharedMemorySize,
                         SMEM_FLOATS * (int)sizeof(float));
    dim3 agrid(T_ / LT, H_, B_);
    attn_fused<<<agrid, 128, SMEM_FLOATS * sizeof(float)>>>(
        w1, b1, w2, b2, w3, b3, w4, b4, out);
}

// round 4
// speedup vs baseline: 4.1534x; 1.1485x over previous
#include <cuda_runtime.h>
#include <cuda_bf16.h>

#define B_  2
#define T_  512
#define E_  768
#define H_  12
#define HD_ 64

// scratch: Q, K, V in [B, T, E] layout, values pre-rounded to tf32 (rna)
__device__ float g_qkv[3][B_ * T_ * E_];
// K' = w1-folded K: [b][g][t*8+o][d], tf32-rounded. 25 MB.
__device__ float g_kp[B_ * H_ * T_ * 8 * HD_];

__device__ __forceinline__ unsigned f2tf32(float f) {
    unsigned u;
    asm("cvt.rna.tf32.f32 %0, %1;" : "=r"(u) : "f"(f));
    return u;
}

__device__ __forceinline__ void mma_tf32(
    float& d0, float& d1, float& d2, float& d3,
    unsigned a0, unsigned a1, unsigned a2, unsigned a3,
    unsigned b0, unsigned b1)
{
    asm volatile(
        "mma.sync.aligned.m16n8k8.row.col.f32.tf32.tf32.f32 "
        "{%0,%1,%2,%3}, {%4,%5,%6,%7}, {%8,%9}, {%0,%1,%2,%3};"
        : "+f"(d0), "+f"(d1), "+f"(d2), "+f"(d3)
        : "r"(a0), "r"(a1), "r"(a2), "r"(a3), "r"(b0), "r"(b1));
}

__device__ __forceinline__ unsigned smem_u32(const void* p) {
    return (unsigned)__cvta_generic_to_shared(p);
}
__device__ __forceinline__ void cp_async16(unsigned s, const void* g) {
    asm volatile("cp.async.cg.shared.global [%0], [%1], 16;" :: "r"(s), "l"(g));
}
__device__ __forceinline__ void cp_commit() {
    asm volatile("cp.async.commit_group;");
}
__device__ __forceinline__ void cp_wait_all() {
    asm volatile("cp.async.wait_group 0;");
}

// ---------------------------------------------------------------------------
// Kernel 1: QKV projection via tf32 mma.  out = round_tf32(X @ W^T + b)
// ---------------------------------------------------------------------------
__global__ __launch_bounds__(256) void qkv_mma(
    const float* __restrict__ X,
    const float* __restrict__ wq, const float* __restrict__ bq,
    const float* __restrict__ wk, const float* __restrict__ bk,
    const float* __restrict__ wv, const float* __restrict__ bv)
{
    const float* W; const float* bias; float* out;
    if (blockIdx.z == 0)      { W = wq; bias = bq; out = g_qkv[0]; }
    else if (blockIdx.z == 1) { W = wk; bias = bk; out = g_qkv[1]; }
    else                      { W = wv; bias = bv; out = g_qkv[2]; }

    __shared__ float Xs[64 * 36];
    __shared__ float Wsh[64 * 36];
    const unsigned* Xu = (const unsigned*)Xs;
    const unsigned* Wu = (const unsigned*)Wsh;

    const int tid  = threadIdx.x;
    const int lane = tid & 31;
    const int warp = tid >> 5;
    const int gid  = lane >> 2;
    const int tig  = lane & 3;
    const int mw   = warp & 3;
    const int nw   = warp >> 2;

    const int m0 = blockIdx.y * 64;
    const int n0 = blockIdx.x * 64;
    const int lr = tid >> 2;
    const int lc = (tid & 3) << 2;

    float acc[4][4];
    #pragma unroll
    for (int nb = 0; nb < 4; nb++)
        #pragma unroll
        for (int i = 0; i < 4; i++) acc[nb][i] = 0.f;

    for (int k0 = 0; k0 < E_; k0 += 32) {
        float4 xv[2], wv4[2];
        #pragma unroll
        for (int h = 0; h < 2; h++) {
            xv[h]  = *(const float4*)&X[(m0 + lr) * E_ + k0 + lc + h * 16];
            wv4[h] = *(const float4*)&W[(n0 + lr) * E_ + k0 + lc + h * 16];
        }
        __syncthreads();
        #pragma unroll
        for (int h = 0; h < 2; h++) {
            float4 xc, wc;
            xc.x = __uint_as_float(f2tf32(xv[h].x));  xc.y = __uint_as_float(f2tf32(xv[h].y));
            xc.z = __uint_as_float(f2tf32(xv[h].z));  xc.w = __uint_as_float(f2tf32(xv[h].w));
            wc.x = __uint_as_float(f2tf32(wv4[h].x)); wc.y = __uint_as_float(f2tf32(wv4[h].y));
            wc.z = __uint_as_float(f2tf32(wv4[h].z)); wc.w = __uint_as_float(f2tf32(wv4[h].w));
            *(float4*)&Xs[lr * 36 + lc + h * 16]  = xc;
            *(float4*)&Wsh[lr * 36 + lc + h * 16] = wc;
        }
        __syncthreads();

        #pragma unroll
        for (int ks = 0; ks < 4; ks++) {
            const int arow = mw * 16 + gid;
            unsigned a0 = Xu[arow * 36 + ks * 8 + tig];
            unsigned a1 = Xu[(arow + 8) * 36 + ks * 8 + tig];
            unsigned a2 = Xu[arow * 36 + ks * 8 + tig + 4];
            unsigned a3 = Xu[(arow + 8) * 36 + ks * 8 + tig + 4];
            #pragma unroll
            for (int nb = 0; nb < 4; nb++) {
                const int brow = nw * 32 + nb * 8 + gid;
                unsigned b0 = Wu[brow * 36 + ks * 8 + tig];
                unsigned b1 = Wu[brow * 36 + ks * 8 + tig + 4];
                mma_tf32(acc[nb][0], acc[nb][1], acc[nb][2], acc[nb][3],
                         a0, a1, a2, a3, b0, b1);
            }
        }
    }

    #pragma unroll
    for (int nb = 0; nb < 4; nb++) {
        const int c = n0 + nw * 32 + nb * 8 + 2 * tig;
        const float bz0 = bias[c], bz1 = bias[c + 1];
        const int r0 = m0 + mw * 16 + gid;
        float2 o0, o1;
        o0.x = __uint_as_float(f2tf32(acc[nb][0] + bz0));
        o0.y = __uint_as_float(f2tf32(acc[nb][1] + bz1));
        o1.x = __uint_as_float(f2tf32(acc[nb][2] + bz0));
        o1.y = __uint_as_float(f2tf32(acc[nb][3] + bz1));
        *(float2*)&out[r0 * E_ + c]       = o0;
        *(float2*)&out[(r0 + 8) * E_ + c] = o1;
    }
}

// ---------------------------------------------------------------------------
// Kernel 1.5: K' precompute. K'[b,g,t,o,d] = sum_kh w1[g*8+o,kh]*K[b,t,kh*64+d]/sqrt(E)
// grid (T/8, B), 256 threads. K tile (8 rows x 768) staged in smem.
// ---------------------------------------------------------------------------
__global__ __launch_bounds__(256) void kprep(const float* __restrict__ w1)
{
    __shared__ float Ksm[8 * 768];
    __shared__ float w1s[1152];
    const int b  = blockIdx.y;
    const int t0 = blockIdx.x * 8;
    const int tid = threadIdx.x;
    const float inv_scale = 0.03608439182435161f;  // 1/sqrt(768)

    #pragma unroll
    for (int i = 0; i < 6; i++) {
        int idx = tid + i * 256;               // float4 index, 1536 total
        int r = idx / 192, c = (idx % 192) << 2;
        *(float4*)&Ksm[r * 768 + c] =
            *(const float4*)&g_qkv[1][(size_t)(b * T_ + t0 + r) * E_ + c];
    }
    for (int idx = tid; idx < 1152; idx += 256) w1s[idx] = w1[idx] * inv_scale;
    __syncthreads();

    #pragma unroll 2
    for (int i = 0; i < 48; i++) {
        int idx = tid + i * 256;               // float4 outputs, 12288 total
        int t   = idx / 1536;
        int rem = idx - t * 1536;
        int go  = rem >> 4;                    // g*8+o, 0..95
        int c   = (rem & 15) << 2;
        float4 acc = make_float4(0.f, 0.f, 0.f, 0.f);
        #pragma unroll
        for (int kh = 0; kh < 12; kh++) {
            float w = w1s[go * 12 + kh];
            float4 kv = *(const float4*)&Ksm[t * 768 + kh * 64 + c];
            acc.x = fmaf(w, kv.x, acc.x);
            acc.y = fmaf(w, kv.y, acc.y);
            acc.z = fmaf(w, kv.z, acc.z);
            acc.w = fmaf(w, kv.w, acc.w);
        }
        acc.x = __uint_as_float(f2tf32(acc.x));
        acc.y = __uint_as_float(f2tf32(acc.y));
        acc.z = __uint_as_float(f2tf32(acc.z));
        acc.w = __uint_as_float(f2tf32(acc.w));
        int g = go >> 3, o = go & 7;
        *(float4*)&g_kp[((size_t)(b * H_ + g) * (T_ * 8) + (size_t)(t0 + t) * 8 + o) * HD_ + c] = acc;
    }
}

// ---------------------------------------------------------------------------
// Kernel 2: fused hidden(mma over (t,o)) -> MLP tail (regs+shfl) -> ctx(mma).
// grid (T/32, H, B), 256 threads (8 warps): warp = (lb in 0..1, wn in 0..3).
// scores: warp does 16l x {4t x 8o}; ctx: warp does 16l x 16d.
// ---------------------------------------------------------------------------
#define TK 16
#define LT 32
#define VS_OFF 8704                 // Ks: 128*68 = 8704
#define WS_OFF 9792                 // Vs: 16*68 = 1088
#define SMEM_FLOATS 10432           // Ws: 32*20 = 640  -> 41728 bytes

__global__ __launch_bounds__(256, 3) void attn_fused(
    const float* __restrict__ b1, const float* __restrict__ w2,
    const float* __restrict__ b2, const float* __restrict__ w3,
    const float* __restrict__ b3, const float* __restrict__ w4,
    const float* __restrict__ b4, float* __restrict__ out)
{
    extern __shared__ float sm[];
    float* Ks = sm;
    float* Vs = sm + VS_OFF;
    float* Ws = sm + WS_OFF;
    const unsigned* Ku  = (const unsigned*)Ks;
    const unsigned* Vu  = (const unsigned*)Vs;
    const unsigned* Wsu = (const unsigned*)Ws;

    const int b  = blockIdx.z;
    const int g  = blockIdx.y;
    const int l0 = blockIdx.x * LT;
    const int tid  = threadIdx.x;
    const int lane = tid & 31;
    const int warp = tid >> 5;
    const int gid  = lane >> 2;   // 0..7
    const int tig  = lane & 3;    // 0..3
    const int lb   = warp >> 2;   // 0..1  (16-row half)
    const int wn   = warp & 3;    // 0..3  (4-key / 16-d slice)

    // per-thread constants (accumulator cols are o = 2*tig, 2*tig+1)
    const float b1lo = b1[g * 8 + 2 * tig], b1hi = b1[g * 8 + 2 * tig + 1];
    const float w2lo = w2[g * 8 + 2 * tig], w2hi = w2[g * 8 + 2 * tig + 1];
    const float b2r = b2[g], b4r = b4[g];
    float w3r[4], b3r[4], w4r[4];
    #pragma unroll
    for (int j = 0; j < 4; j++) {
        w3r[j] = w3[g * 4 + j]; b3r[j] = b3[g * 4 + j]; w4r[j] = w4[g * 4 + j];
    }

    // Q A-fragments in registers (loop-invariant)
    unsigned a[8][4];
    {
        const float* qb = g_qkv[0] + (size_t)(b * T_ + l0 + lb * 16 + gid) * E_ + g * HD_;
        #pragma unroll
        for (int ks = 0; ks < 8; ks++) {
            a[ks][0] = __float_as_uint(qb[ks * 8 + tig]);
            a[ks][1] = __float_as_uint(qb[8 * E_ + ks * 8 + tig]);
            a[ks][2] = __float_as_uint(qb[ks * 8 + tig + 4]);
            a[ks][3] = __float_as_uint(qb[8 * E_ + ks * 8 + tig + 4]);
        }
    }

    const float* Kg = g_kp + (size_t)(b * H_ + g) * (T_ * 8 * HD_);
    const float* Vp = g_qkv[2];
    const unsigned ks_s = smem_u32(Ks);
    const unsigned vs_s = smem_u32(Vs);

    // stage tile 0 (K' tile: 2048 float4 contiguous in gmem; V tile: 256 float4)
    {
        #pragma unroll
        for (int i = 0; i < 8; i++) {
            int idx = tid + i * 256;
            int r = idx >> 4, c = (idx & 15) << 2;
            cp_async16(ks_s + (unsigned)(r * 68 + c) * 4, Kg + (size_t)idx * 4);
        }
        int vr = tid >> 4, vc = (tid & 15) << 2;
        cp_async16(vs_s + (unsigned)(vr * 68 + vc) * 4,
                   Vp + (size_t)(b * T_ + vr) * E_ + g * HD_ + vc);
        cp_commit();
        cp_wait_all();
    }
    __syncthreads();

    float cacc[2][4] = {};

    for (int t0 = 0; t0 < T_; t0 += TK) {
        const bool more = (t0 + TK) < T_;

        // ---- hidden = b1 + Q.K'  (mma over n=(t,o)), then MLP tail ----
        #pragma unroll
        for (int nb = 0; nb < 4; nb++) {
            const int t = wn * 4 + nb;
            float d0 = b1lo, d1 = b1hi, d2 = b1lo, d3 = b1hi;
            const int koff = (t * 8 + gid) * 68;
            #pragma unroll
            for (int ks = 0; ks < 8; ks++) {
                unsigned b0v = Ku[koff + ks * 8 + tig];
                unsigned b1v = Ku[koff + ks * 8 + tig + 4];
                mma_tf32(d0, d1, d2, d3,
                         a[ks][0], a[ks][1], a[ks][2], a[ks][3], b0v, b1v);
            }
            // w2 . relu(h), reduce over 8 o (pairs local + quad shuffle)
            float u0 = fmaf(w2lo, fmaxf(d0, 0.f), w2hi * fmaxf(d1, 0.f));
            float u1 = fmaf(w2lo, fmaxf(d2, 0.f), w2hi * fmaxf(d3, 0.f));
            u0 += __shfl_xor_sync(0xffffffff, u0, 1);
            u0 += __shfl_xor_sync(0xffffffff, u0, 2);
            u1 += __shfl_xor_sync(0xffffffff, u1, 1);
            u1 += __shfl_xor_sync(0xffffffff, u1, 2);
            float a20 = u0 + b2r, a21 = u1 + b2r;
            float wv0 = b4r, wv1 = b4r;
            #pragma unroll
            for (int j = 0; j < 4; j++) {
                wv0 = fmaf(w4r[j], fmaxf(fmaf(w3r[j], a20, b3r[j]), 0.f), wv0);
                wv1 = fmaf(w4r[j], fmaxf(fmaf(w3r[j], a21, b3r[j]), 0.f), wv1);
            }
            if (tig == 0) {
                Ws[(lb * 16 + gid) * 20 + t]     = __uint_as_float(f2tf32(wv0));
                Ws[(lb * 16 + gid + 8) * 20 + t] = __uint_as_float(f2tf32(wv1));
            }
        }
        __syncthreads();   // Ws ready; all warps done reading Ks

        // prefetch next K' tile (ctx never touches Ks)
        if (more) {
            const float* kt = Kg + (size_t)(t0 + TK) * 8 * HD_;
            #pragma unroll
            for (int i = 0; i < 8; i++) {
                int idx = tid + i * 256;
                int r = idx >> 4, c = (idx & 15) << 2;
                cp_async16(ks_s + (unsigned)(r * 68 + c) * 4, kt + (size_t)idx * 4);
            }
            cp_commit();
        }

        // ---- ctx: cacc += Ws[32,16] @ Vs[16,64]; warp covers 16l x 16d ----
        #pragma unroll
        for (int ks = 0; ks < 2; ks++) {
            const int wr = (lb * 16 + gid) * 20 + ks * 8 + tig;
            unsigned wa0 = Wsu[wr];
            unsigned wa1 = Wsu[wr + 8 * 20];
            unsigned wa2 = Wsu[wr + 4];
            unsigned wa3 = Wsu[wr + 8 * 20 + 4];
            #pragma unroll
            for (int nb2 = 0; nb2 < 2; nb2++) {
                const int db = (wn * 2 + nb2) * 8;
                unsigned b0v = Vu[(ks * 8 + tig) * 68 + db + gid];
                unsigned b1v = Vu[(ks * 8 + tig + 4) * 68 + db + gid];
                mma_tf32(cacc[nb2][0], cacc[nb2][1], cacc[nb2][2], cacc[nb2][3],
                         wa0, wa1, wa2, wa3, b0v, b1v);
            }
        }
        __syncthreads();   // done reading Vs & Ws

        if (more) {
            int vr = tid >> 4, vc = (tid & 15) << 2;
            cp_async16(vs_s + (unsigned)(vr * 68 + vc) * 4,
                       Vp + (size_t)(b * T_ + t0 + TK + vr) * E_ + g * HD_ + vc);
            cp_commit();
            cp_wait_all();
            __syncthreads();
        }
    }

    // ---- store ctx ----
    #pragma unroll
    for (int nb2 = 0; nb2 < 2; nb2++) {
        const int row0 = b * T_ + l0 + lb * 16 + gid;
        const int col  = g * HD_ + (wn * 2 + nb2) * 8 + 2 * tig;
        *(float2*)&out[(size_t)row0 * E_ + col] =
            make_float2(cacc[nb2][0], cacc[nb2][1]);
        *(float2*)&out[(size_t)(row0 + 8) * E_ + col] =
            make_float2(cacc[nb2][2], cacc[nb2][3]);
    }
}

// ---------------------------------------------------------------------------
extern "C" void kernel_launch(void* const* d_in, const int* in_sizes, int n_in,
                              void* d_out, int out_size)
{
    const float* x  = (const float*)d_in[0];
    const float* wq = (const float*)d_in[1];
    const float* bq = (const float*)d_in[2];
    const float* wk = (const float*)d_in[3];
    const float* bk = (const float*)d_in[4];
    const float* wv = (const float*)d_in[5];
    const float* bv = (const float*)d_in[6];
    const float* w1 = (const float*)d_in[7];
    const float* b1 = (const float*)d_in[8];
    const float* w2 = (const float*)d_in[9];
    const float* b2 = (const float*)d_in[10];
    const float* w3 = (const float*)d_in[11];
    const float* b3 = (const float*)d_in[12];
    const float* w4 = (const float*)d_in[13];
    const float* b4 = (const float*)d_in[14];
    float* out = (float*)d_out;

    dim3 ggrid(E_ / 64, (B_ * T_) / 64, 3);
    qkv_mma<<<ggrid, 256>>>(x, wq, bq, wk, bk, wv, bv);

    dim3 pgrid(T_ / 8, B_);
    kprep<<<pgrid, 256>>>(w1);

    cudaFuncSetAttribute(attn_fused, cudaFuncAttributeMaxDynamicSharedMemorySize,
                         SMEM_FLOATS * (int)sizeof(float));
    dim3 agrid(T_ / LT, H_, B_);
    attn_fused<<<agrid, 256, SMEM_FLOATS * sizeof(float)>>>(
        b1, w2, b2, w3, b3, w4, b4, out);
}

// round 5
// speedup vs baseline: 5.2785x; 1.2709x over previous
#include <cuda_runtime.h>
#include <cuda_bf16.h>

#define B_  2
#define T_  512
#define E_  768
#define H_  12
#define HD_ 64

// Q, K, V in [B, T, E]; Q and K stored with k-permuted layout, V normal.
__device__ float g_qkv[3][B_ * T_ * E_];
// K' = w1-folded K: [b][g][t*8+o][d] (d permuted), tf32-rounded.
__device__ float g_kp[B_ * H_ * T_ * 8 * HD_];
// tf32-rounded + k-permuted copies of X and the three weight matrices.
__device__ float g_xp[B_ * T_ * E_];
__device__ float g_wp[3 * E_ * E_];

__device__ __forceinline__ unsigned f2tf32(float f) {
    unsigned u;
    asm("cvt.rna.tf32.f32 %0, %1;" : "=r"(u) : "f"(f));
    return u;
}

__device__ __forceinline__ void mma_tf32(
    float& d0, float& d1, float& d2, float& d3,
    unsigned a0, unsigned a1, unsigned a2, unsigned a3,
    unsigned b0, unsigned b1)
{
    asm volatile(
        "mma.sync.aligned.m16n8k8.row.col.f32.tf32.tf32.f32 "
        "{%0,%1,%2,%3}, {%4,%5,%6,%7}, {%8,%9}, {%0,%1,%2,%3};"
        : "+f"(d0), "+f"(d1), "+f"(d2), "+f"(d3)
        : "r"(a0), "r"(a1), "r"(a2), "r"(a3), "r"(b0), "r"(b1));
}

__device__ __forceinline__ unsigned smem_u32(const void* p) {
    return (unsigned)__cvta_generic_to_shared(p);
}
__device__ __forceinline__ void cp_async16(unsigned s, const void* g) {
    asm volatile("cp.async.cg.shared.global [%0], [%1], 16;" :: "r"(s), "l"(g));
}
__device__ __forceinline__ void cp_commit()  { asm volatile("cp.async.commit_group;"); }
__device__ __forceinline__ void cp_wait1()   { asm volatile("cp.async.wait_group 1;"); }
__device__ __forceinline__ void cp_wait_all(){ asm volatile("cp.async.wait_group 0;"); }

// permutation within 16-element k-chunks (involution)
__device__ __forceinline__ int kperm(int c) {
    return (c & ~15) | (((c & 3) << 2) | ((c >> 2) & 3));
}

// ---------------------------------------------------------------------------
// Kernel 0: round X / W to tf32 and store with k-permuted columns.
// grid (1024, 4), block 192. y=0: X; y=1..3: wq/wk/wv.
// ---------------------------------------------------------------------------
__global__ __launch_bounds__(192) void prep(
    const float* __restrict__ x,  const float* __restrict__ wq,
    const float* __restrict__ wk, const float* __restrict__ wv)
{
    const int z = blockIdx.y;
    const float* src; float* dst; int nrows;
    if (z == 0)      { src = x;  dst = g_xp;                nrows = B_ * T_; }
    else if (z == 1) { src = wq; dst = g_wp;                nrows = E_; }
    else if (z == 2) { src = wk; dst = g_wp + E_ * E_;      nrows = E_; }
    else             { src = wv; dst = g_wp + 2 * E_ * E_;  nrows = E_; }
    const int row = blockIdx.x;
    if (row >= nrows) return;
    const int c0 = threadIdx.x * 4;          // 0..764, 4s-aligned
    float4 v = *(const float4*)&src[(size_t)row * E_ + c0];
    float* d = dst + (size_t)row * E_;
    d[kperm(c0 + 0)] = __uint_as_float(f2tf32(v.x));
    d[kperm(c0 + 1)] = __uint_as_float(f2tf32(v.y));
    d[kperm(c0 + 2)] = __uint_as_float(f2tf32(v.z));
    d[kperm(c0 + 3)] = __uint_as_float(f2tf32(v.w));
}

// ---------------------------------------------------------------------------
// Kernel 1: QKV projection, cp.async 2-stage pipeline, float4 fragments.
// Tile 64x64, BK=32, 256 threads, warp tile 16m x 32n.
// Q/K outputs stored k-permuted; V normal. All outputs tf32-rounded.
// ---------------------------------------------------------------------------
#define QKV_STG 3072          // 64 rows * 48 floats per matrix per stage

__global__ __launch_bounds__(256) void qkv_mma(
    const float* __restrict__ bq, const float* __restrict__ bk,
    const float* __restrict__ bv)
{
    extern __shared__ float sm[];           // [2 stages][X | W] = 4*3072 floats
    const int z = blockIdx.z;
    const float* Wg = g_wp + (size_t)z * E_ * E_;
    const float* bias = (z == 0) ? bq : (z == 1) ? bk : bv;
    float* out = g_qkv[z];

    const int tid  = threadIdx.x;
    const int lane = tid & 31;
    const int warp = tid >> 5;
    const int gid  = lane >> 2;
    const int tig  = lane & 3;
    const int mw   = warp & 3;
    const int nw   = warp >> 2;
    const int m0 = blockIdx.y * 64;
    const int n0 = blockIdx.x * 64;

    const unsigned sm_s = smem_u32(sm);
    const int srow = tid >> 3;              // 0..31 -> two rows handled
    const int scol = (tid & 7) << 2;        // 0,4,...,28

    auto stage = [&](int it) {
        const int buf = it & 1;
        const int k0 = it * 32;
        #pragma unroll
        for (int i = 0; i < 2; i++) {
            const int row = srow + i * 32;
            cp_async16(sm_s + (unsigned)(buf * QKV_STG + row * 48 + scol) * 4,
                       g_xp + (size_t)(m0 + row) * E_ + k0 + scol);
            cp_async16(sm_s + (unsigned)(2 * QKV_STG + buf * QKV_STG + row * 48 + scol) * 4,
                       Wg + (size_t)(n0 + row) * E_ + k0 + scol);
        }
        cp_commit();
    };

    float acc[4][4];
    #pragma unroll
    for (int nb = 0; nb < 4; nb++)
        #pragma unroll
        for (int i = 0; i < 4; i++) acc[nb][i] = 0.f;

    stage(0);
    stage(1);

    for (int it = 0; it < 24; it++) {
        if (it == 23) cp_wait_all(); else cp_wait1();
        __syncthreads();
        const float4* X4 = (const float4*)(sm + (it & 1) * QKV_STG);
        const float4* W4 = (const float4*)(sm + 2 * QKV_STG + (it & 1) * QKV_STG);
        #pragma unroll
        for (int kc = 0; kc < 2; kc++) {
            float4 fa = X4[(mw * 16 + gid) * 12 + kc * 4 + tig];
            float4 fb = X4[(mw * 16 + gid + 8) * 12 + kc * 4 + tig];
            #pragma unroll
            for (int nb = 0; nb < 4; nb++) {
                float4 gg = W4[(nw * 32 + nb * 8 + gid) * 12 + kc * 4 + tig];
                mma_tf32(acc[nb][0], acc[nb][1], acc[nb][2], acc[nb][3],
                         __float_as_uint(fa.x), __float_as_uint(fb.x),
                         __float_as_uint(fa.y), __float_as_uint(fb.y),
                         __float_as_uint(gg.x), __float_as_uint(gg.y));
                mma_tf32(acc[nb][0], acc[nb][1], acc[nb][2], acc[nb][3],
                         __float_as_uint(fa.z), __float_as_uint(fb.z),
                         __float_as_uint(fa.w), __float_as_uint(fb.w),
                         __float_as_uint(gg.z), __float_as_uint(gg.w));
            }
        }
        __syncthreads();
        if (it + 2 < 24) stage(it + 2);
    }

    // epilogue
    #pragma unroll
    for (int nb = 0; nb < 4; nb++) {
        const int c = n0 + nw * 32 + nb * 8 + 2 * tig;
        const float bz0 = bias[c], bz1 = bias[c + 1];
        const int r0 = m0 + mw * 16 + gid;
        float v00 = __uint_as_float(f2tf32(acc[nb][0] + bz0));
        float v01 = __uint_as_float(f2tf32(acc[nb][1] + bz1));
        float v10 = __uint_as_float(f2tf32(acc[nb][2] + bz0));
        float v11 = __uint_as_float(f2tf32(acc[nb][3] + bz1));
        if (z < 2) {   // Q, K: store k-permuted columns
            const int p0 = kperm(c), p1 = kperm(c + 1);
            out[(size_t)r0 * E_ + p0]       = v00;
            out[(size_t)r0 * E_ + p1]       = v01;
            out[(size_t)(r0 + 8) * E_ + p0] = v10;
            out[(size_t)(r0 + 8) * E_ + p1] = v11;
        } else {       // V: normal layout
            *(float2*)&out[(size_t)r0 * E_ + c]       = make_float2(v00, v01);
            *(float2*)&out[(size_t)(r0 + 8) * E_ + c] = make_float2(v10, v11);
        }
    }
}

// ---------------------------------------------------------------------------
// Kernel 1.5: K' precompute (positionwise fold -> stays permuted).
// ---------------------------------------------------------------------------
__global__ __launch_bounds__(256) void kprep(const float* __restrict__ w1)
{
    __shared__ float Ksm[8 * 768];
    __shared__ float w1s[1152];
    const int b  = blockIdx.y;
    const int t0 = blockIdx.x * 8;
    const int tid = threadIdx.x;
    const float inv_scale = 0.03608439182435161f;

    #pragma unroll
    for (int i = 0; i < 6; i++) {
        int idx = tid + i * 256;
        int r = idx / 192, c = (idx % 192) << 2;
        *(float4*)&Ksm[r * 768 + c] =
            *(const float4*)&g_qkv[1][(size_t)(b * T_ + t0 + r) * E_ + c];
    }
    for (int idx = tid; idx < 1152; idx += 256) w1s[idx] = w1[idx] * inv_scale;
    __syncthreads();

    #pragma unroll 2
    for (int i = 0; i < 48; i++) {
        int idx = tid + i * 256;
        int t   = idx / 1536;
        int rem = idx - t * 1536;
        int go  = rem >> 4;
        int c   = (rem & 15) << 2;
        float4 acc = make_float4(0.f, 0.f, 0.f, 0.f);
        #pragma unroll
        for (int kh = 0; kh < 12; kh++) {
            float w = w1s[go * 12 + kh];
            float4 kv = *(const float4*)&Ksm[t * 768 + kh * 64 + c];
            acc.x = fmaf(w, kv.x, acc.x);
            acc.y = fmaf(w, kv.y, acc.y);
            acc.z = fmaf(w, kv.z, acc.z);
            acc.w = fmaf(w, kv.w, acc.w);
        }
        acc.x = __uint_as_float(f2tf32(acc.x));
        acc.y = __uint_as_float(f2tf32(acc.y));
        acc.z = __uint_as_float(f2tf32(acc.z));
        acc.w = __uint_as_float(f2tf32(acc.w));
        int g = go >> 3, o = go & 7;
        *(float4*)&g_kp[((size_t)(b * H_ + g) * (T_ * 8) + (size_t)(t0 + t) * 8 + o) * HD_ + c] = acc;
    }
}

// ---------------------------------------------------------------------------
// Kernel 2: fused hidden(mma) -> MLP tail -> ctx(mma). float4 fragments.
// grid (T/32, H, B), 256 threads; Ks stride 80 (conflict-free LDS.128).
// ---------------------------------------------------------------------------
#define TK 16
#define LT 32
#define KS_STRIDE 80
#define VS_OFF 10240               // Ks: 128*80
#define VS_BUF 1088                // 16*68
#define WS_OFF 12416               // Vs: 2*1088
#define SMEM_FLOATS 13056          // + Ws 32*20 = 640  -> 52224 bytes

__global__ __launch_bounds__(256, 3) void attn_fused(
    const float* __restrict__ b1, const float* __restrict__ w2,
    const float* __restrict__ b2, const float* __restrict__ w3,
    const float* __restrict__ b3, const float* __restrict__ w4,
    const float* __restrict__ b4, float* __restrict__ out)
{
    extern __shared__ float sm[];
    float* Ks = sm;
    float* Vs = sm + VS_OFF;
    float* Ws = sm + WS_OFF;
    const float4*  Ku4 = (const float4*)Ks;
    const unsigned* Vu  = (const unsigned*)Vs;
    const unsigned* Wsu = (const unsigned*)Ws;

    const int b  = blockIdx.z;
    const int g  = blockIdx.y;
    const int l0 = blockIdx.x * LT;
    const int tid  = threadIdx.x;
    const int lane = tid & 31;
    const int warp = tid >> 5;
    const int gid  = lane >> 2;
    const int tig  = lane & 3;
    const int lb   = warp >> 2;   // 0..1
    const int wn   = warp & 3;    // 0..3

    const float b1lo = __ldg(&b1[g * 8 + 2 * tig]);
    const float b1hi = __ldg(&b1[g * 8 + 2 * tig + 1]);
    const float w2lo = __ldg(&w2[g * 8 + 2 * tig]);
    const float w2hi = __ldg(&w2[g * 8 + 2 * tig + 1]);
    const float b2r = __ldg(&b2[g]), b4r = __ldg(&b4[g]);
    float w3r[4], b3r[4], w4r[4];
    #pragma unroll
    for (int j = 0; j < 4; j++) {
        w3r[j] = __ldg(&w3[g * 4 + j]);
        b3r[j] = __ldg(&b3[g * 4 + j]);
        w4r[j] = __ldg(&w4[g * 4 + j]);
    }

    const int row0 = b * T_ + l0 + lb * 16 + gid;
    const float4* q4a = (const float4*)(g_qkv[0] + (size_t)row0 * E_ + g * HD_);
    const float4* q4b = (const float4*)(g_qkv[0] + (size_t)(row0 + 8) * E_ + g * HD_);

    const float* Kg = g_kp + (size_t)(b * H_ + g) * (T_ * 8 * HD_);
    const float* Vp = g_qkv[2];
    const unsigned ks_s = smem_u32(Ks);
    const unsigned vs_s = smem_u32(Vs);

    auto stage = [&](int tile) {
        const float* kt = Kg + (size_t)tile * (TK * 8 * HD_);
        #pragma unroll
        for (int i = 0; i < 8; i++) {
            int idx = tid + i * 256;
            int r = idx >> 4, c = (idx & 15) << 2;
            cp_async16(ks_s + (unsigned)(r * KS_STRIDE + c) * 4, kt + (size_t)idx * 4);
        }
        int vr = tid >> 4, vc = (tid & 15) << 2;
        cp_async16(vs_s + (unsigned)((tile & 1) * VS_BUF + vr * 68 + vc) * 4,
                   Vp + (size_t)(b * T_ + tile * TK + vr) * E_ + g * HD_ + vc);
        cp_commit();
    };

    stage(0);
    cp_wait_all();
    __syncthreads();

    float cacc[2][4] = {};

    for (int ti = 0; ti < T_ / TK; ti++) {
        const bool more = (ti + 1) < (T_ / TK);

        // ---- hidden = b1 + Q.K' (mma), kc outer so Q frags are transient ----
        float d[4][4];
        #pragma unroll
        for (int nb = 0; nb < 4; nb++) {
            d[nb][0] = b1lo; d[nb][1] = b1hi; d[nb][2] = b1lo; d[nb][3] = b1hi;
        }
        #pragma unroll
        for (int kc = 0; kc < 4; kc++) {
            float4 qa = __ldg(&q4a[kc * 4 + tig]);
            float4 qb = __ldg(&q4b[kc * 4 + tig]);
            #pragma unroll
            for (int nb = 0; nb < 4; nb++) {
                const int t = wn * 4 + nb;
                float4 gk = Ku4[(t * 8 + gid) * (KS_STRIDE / 4) + kc * 4 + tig];
                mma_tf32(d[nb][0], d[nb][1], d[nb][2], d[nb][3],
                         __float_as_uint(qa.x), __float_as_uint(qb.x),
                         __float_as_uint(qa.y), __float_as_uint(qb.y),
                         __float_as_uint(gk.x), __float_as_uint(gk.y));
                mma_tf32(d[nb][0], d[nb][1], d[nb][2], d[nb][3],
                         __float_as_uint(qa.z), __float_as_uint(qb.z),
                         __float_as_uint(qa.w), __float_as_uint(qb.w),
                         __float_as_uint(gk.z), __float_as_uint(gk.w));
            }
        }

        // ---- MLP tail ----
        #pragma unroll
        for (int nb = 0; nb < 4; nb++) {
            const int t = wn * 4 + nb;
            float u0 = fmaf(w2lo, fmaxf(d[nb][0], 0.f), w2hi * fmaxf(d[nb][1], 0.f));
            float u1 = fmaf(w2lo, fmaxf(d[nb][2], 0.f), w2hi * fmaxf(d[nb][3], 0.f));
            u0 += __shfl_xor_sync(0xffffffff, u0, 1);
            u0 += __shfl_xor_sync(0xffffffff, u0, 2);
            u1 += __shfl_xor_sync(0xffffffff, u1, 1);
            u1 += __shfl_xor_sync(0xffffffff, u1, 2);
            float a20 = u0 + b2r, a21 = u1 + b2r;
            float wv0 = b4r, wv1 = b4r;
            #pragma unroll
            for (int j = 0; j < 4; j++) {
                wv0 = fmaf(w4r[j], fmaxf(fmaf(w3r[j], a20, b3r[j]), 0.f), wv0);
                wv1 = fmaf(w4r[j], fmaxf(fmaf(w3r[j], a21, b3r[j]), 0.f), wv1);
            }
            if (tig == 0) {
                Ws[(lb * 16 + gid) * 20 + t]     = __uint_as_float(f2tf32(wv0));
                Ws[(lb * 16 + gid + 8) * 20 + t] = __uint_as_float(f2tf32(wv1));
            }
        }
        __syncthreads();   // Ws ready; all warps done reading Ks

        if (more) stage(ti + 1);   // overwrites Ks + other V buffer

        // ---- ctx: cacc += Ws[32,16] @ Vs[16,64] ----
        const unsigned* Vb = Vu + (ti & 1) * VS_BUF;
        #pragma unroll
        for (int ks = 0; ks < 2; ks++) {
            const int wr = (lb * 16 + gid) * 20 + ks * 8 + tig;
            unsigned wa0 = Wsu[wr];
            unsigned wa1 = Wsu[wr + 8 * 20];
            unsigned wa2 = Wsu[wr + 4];
            unsigned wa3 = Wsu[wr + 8 * 20 + 4];
            #pragma unroll
            for (int nb2 = 0; nb2 < 2; nb2++) {
                const int db = (wn * 2 + nb2) * 8;
                unsigned b0v = Vb[(ks * 8 + tig) * 68 + db + gid];
                unsigned b1v = Vb[(ks * 8 + tig + 4) * 68 + db + gid];
                mma_tf32(cacc[nb2][0], cacc[nb2][1], cacc[nb2][2], cacc[nb2][3],
                         wa0, wa1, wa2, wa3, b0v, b1v);
            }
        }

        if (more) cp_wait_all();
        __syncthreads();
    }

    #pragma unroll
    for (int nb2 = 0; nb2 < 2; nb2++) {
        const int col = g * HD_ + (wn * 2 + nb2) * 8 + 2 * tig;
        *(float2*)&out[(size_t)row0 * E_ + col] =
            make_float2(cacc[nb2][0], cacc[nb2][1]);
        *(float2*)&out[(size_t)(row0 + 8) * E_ + col] =
            make_float2(cacc[nb2][2], cacc[nb2][3]);
    }
}

// ---------------------------------------------------------------------------
extern "C" void kernel_launch(void* const* d_in, const int* in_sizes, int n_in,
                              void* d_out, int out_size)
{
    const float* x  = (const float*)d_in[0];
    const float* wq = (const float*)d_in[1];
    const float* bq = (const float*)d_in[2];
    const float* wk = (const float*)d_in[3];
    const float* bk = (const float*)d_in[4];
    const float* wv = (const float*)d_in[5];
    const float* bv = (const float*)d_in[6];
    const float* w1 = (const float*)d_in[7];
    const float* b1 = (const float*)d_in[8];
    const float* w2 = (const float*)d_in[9];
    const float* b2 = (const float*)d_in[10];
    const float* w3 = (const float*)d_in[11];
    const float* b3 = (const float*)d_in[12];
    const float* w4 = (const float*)d_in[13];
    const float* b4 = (const float*)d_in[14];
    float* out = (float*)d_out;

    dim3 prep_grid(B_ * T_, 4);
    prep<<<prep_grid, 192>>>(x, wq, wk, wv);

    cudaFuncSetAttribute(qkv_mma, cudaFuncAttributeMaxDynamicSharedMemorySize,
                         4 * QKV_STG * (int)sizeof(float));
    dim3 ggrid(E_ / 64, (B_ * T_) / 64, 3);
    qkv_mma<<<ggrid, 256, 4 * QKV_STG * sizeof(float)>>>(bq, bk, bv);

    dim3 pgrid(T_ / 8, B_);
    kprep<<<pgrid, 256>>>(w1);

    cudaFuncSetAttribute(attn_fused, cudaFuncAttributeMaxDynamicSharedMemorySize,
                         SMEM_FLOATS * (int)sizeof(float));
    dim3 agrid(T_ / LT, H_, B_);
    attn_fused<<<agrid, 256, SMEM_FLOATS * sizeof(float)>>>(
        b1, w2, b2, w3, b3, w4, b4, out);
}

// round 6
// speedup vs baseline: 7.0159x; 1.3292x over previous
#include <cuda_runtime.h>
#include <cuda_fp16.h>

#define B_  2
#define T_  512
#define E_  768
#define H_  12
#define HD_ 64

// fp16 tensors. Q/K/X/W use the fp16-mma k-permutation (within 64-blocks,
// chunk-paired). V is stored transposed [B,E,T] with t-permutation. K' is the
// w1-folded K, [b][g][t*8+o][64 d-permuted].
__device__ __half g_xh[B_ * T_ * E_];
__device__ __half g_wh[3 * E_ * E_];
__device__ __half g_qh[B_ * T_ * E_];
__device__ __half g_kh[B_ * T_ * E_];
__device__ __half g_vt[B_ * E_ * T_];
__device__ __half g_kph[B_ * H_ * T_ * 8 * HD_];

// slot of k within a 16-chunk for fp16 mma fragments
__device__ __forceinline__ int s16(int k) {
    return 4 * ((k >> 1) & 3) + 2 * ((k >> 3) & 1) + (k & 1);
}
// position of k within a 64-block: chunk-pairs of 32, thread-slot interleaved
__device__ __forceinline__ int hperm64(int w) {
    int p = w >> 5, c1 = (w >> 4) & 1, k0 = w & 15;
    return p * 32 + ((k0 >> 1) & 3) * 8 + c1 * 4 + ((k0 >> 3) & 1) * 2 + (k0 & 1);
}

__device__ __forceinline__ void mma_f16(
    float& d0, float& d1, float& d2, float& d3,
    unsigned a0, unsigned a1, unsigned a2, unsigned a3,
    unsigned b0, unsigned b1)
{
    asm volatile(
        "mma.sync.aligned.m16n8k16.row.col.f32.f16.f16.f32 "
        "{%0,%1,%2,%3}, {%4,%5,%6,%7}, {%8,%9}, {%0,%1,%2,%3};"
        : "+f"(d0), "+f"(d1), "+f"(d2), "+f"(d3)
        : "r"(a0), "r"(a1), "r"(a2), "r"(a3), "r"(b0), "r"(b1));
}

__device__ __forceinline__ unsigned smem_u32(const void* p) {
    return (unsigned)__cvta_generic_to_shared(p);
}
__device__ __forceinline__ void cp_async16(unsigned s, const void* g) {
    asm volatile("cp.async.cg.shared.global [%0], [%1], 16;" :: "r"(s), "l"(g));
}
__device__ __forceinline__ void cp_commit()   { asm volatile("cp.async.commit_group;"); }
__device__ __forceinline__ void cp_wait1()    { asm volatile("cp.async.wait_group 1;"); }
__device__ __forceinline__ void cp_wait_all() { asm volatile("cp.async.wait_group 0;"); }

// ---------------------------------------------------------------------------
// Kernel 0: fp32 -> fp16 with k-permutation. grid (1024, 4), 192 threads.
// ---------------------------------------------------------------------------
__global__ __launch_bounds__(192) void prep(
    const float* __restrict__ x,  const float* __restrict__ wq,
    const float* __restrict__ wk, const float* __restrict__ wv)
{
    const int z = blockIdx.y;
    const float* src; __half* dst; int nrows;
    if (z == 0)      { src = x;  dst = g_xh;               nrows = B_ * T_; }
    else if (z == 1) { src = wq; dst = g_wh;               nrows = E_; }
    else if (z == 2) { src = wk; dst = g_wh + E_ * E_;     nrows = E_; }
    else             { src = wv; dst = g_wh + 2 * E_ * E_; nrows = E_; }
    const int row = blockIdx.x;
    if (row >= nrows) return;
    const int c0 = threadIdx.x * 4;
    float4 v = *(const float4*)&src[(size_t)row * E_ + c0];
    const int blk = (c0 >> 6) * 64, w = c0 & 63;
    __half* d = dst + (size_t)row * E_;
    *(__half2*)&d[blk + hperm64(w)]     = __floats2half2_rn(v.x, v.y);
    *(__half2*)&d[blk + hperm64(w + 2)] = __floats2half2_rn(v.z, v.w);
}

// ---------------------------------------------------------------------------
// Kernel 1: QKV projection, fp16 mma, 2-stage cp.async pipeline.
// Tile 64x64, BK=32 (one chunk-pair), 256 threads, warp tile 16m x 32n.
// ---------------------------------------------------------------------------
__global__ __launch_bounds__(256) void qkv_mma(
    const float* __restrict__ bq, const float* __restrict__ bk,
    const float* __restrict__ bv)
{
    __shared__ __align__(16) __half sh[8192];   // X 2x2048 | W 2x2048 halves
    const int z = blockIdx.z;
    const __half* Wg = g_wh + (size_t)z * E_ * E_;
    const float* bias = (z == 0) ? bq : (z == 1) ? bk : bv;

    const int tid  = threadIdx.x;
    const int lane = tid & 31;
    const int warp = tid >> 5;
    const int gid  = lane >> 2;
    const int tig  = lane & 3;
    const int mw   = warp & 3;
    const int nw   = warp >> 2;
    const int m0 = blockIdx.y * 64;
    const int n0 = blockIdx.x * 64;

    const unsigned sh_s = smem_u32(sh);
    const int srow = tid & 63;
    const int sslot = tid >> 6;   // 0..3

    auto stage = [&](int it) {
        const int buf = it & 1;
        const int k0 = it * 32;
        const int swz = (sslot ^ (srow & 3)) * 16;  // bytes
        cp_async16(sh_s + (unsigned)((buf * 2048 + srow * 32) * 2 + swz),
                   g_xh + (size_t)(m0 + srow) * E_ + k0 + sslot * 8);
        cp_async16(sh_s + (unsigned)((4096 + buf * 2048 + srow * 32) * 2 + swz),
                   Wg + (size_t)(n0 + srow) * E_ + k0 + sslot * 8);
        cp_commit();
    };

    float acc[4][4];
    #pragma unroll
    for (int nb = 0; nb < 4; nb++)
        #pragma unroll
        for (int i = 0; i < 4; i++) acc[nb][i] = 0.f;

    stage(0);
    stage(1);

    for (int it = 0; it < 24; it++) {
        if (it == 23) cp_wait_all(); else cp_wait1();
        __syncthreads();
        const __half* Xb = sh + (it & 1) * 2048;
        const __half* Wb = sh + 4096 + (it & 1) * 2048;
        const int m = mw * 16 + gid, m8 = m + 8;
        uint4 xa = *(const uint4*)(Xb + m * 32 + ((tig ^ (m & 3)) * 8));
        uint4 xb = *(const uint4*)(Xb + m8 * 32 + ((tig ^ (m8 & 3)) * 8));
        #pragma unroll
        for (int nb = 0; nb < 4; nb++) {
            const int n = nw * 32 + nb * 8 + gid;
            uint4 wb = *(const uint4*)(Wb + n * 32 + ((tig ^ (n & 3)) * 8));
            mma_f16(acc[nb][0], acc[nb][1], acc[nb][2], acc[nb][3],
                    xa.x, xb.x, xa.y, xb.y, wb.x, wb.y);
            mma_f16(acc[nb][0], acc[nb][1], acc[nb][2], acc[nb][3],
                    xa.z, xb.z, xa.w, xb.w, wb.z, wb.w);
        }
        __syncthreads();
        if (it + 2 < 24) stage(it + 2);
    }

    // epilogue: +bias, convert fp16, store (Q/K perm; V transposed+t-perm)
    #pragma unroll
    for (int nb = 0; nb < 4; nb++) {
        const int c = n0 + nw * 32 + nb * 8 + 2 * tig;
        const float bz0 = bias[c], bz1 = bias[c + 1];
        const int r0 = m0 + mw * 16 + gid;
        float v00 = acc[nb][0] + bz0, v01 = acc[nb][1] + bz1;
        float v10 = acc[nb][2] + bz0, v11 = acc[nb][3] + bz1;
        if (z < 2) {
            __half* o = z ? g_kh : g_qh;
            const int pos = (c & ~63) + hperm64(c & 63);
            *(__half2*)&o[(size_t)r0 * E_ + pos]       = __floats2half2_rn(v00, v01);
            *(__half2*)&o[(size_t)(r0 + 8) * E_ + pos] = __floats2half2_rn(v10, v11);
        } else {
            const int bb = r0 >> 9;
            const int t  = r0 & 511, t8 = (r0 + 8) & 511;
            const int tp  = (t & ~15) | s16(t & 15);
            const int tp8 = (t8 & ~15) | s16(t8 & 15);
            g_vt[((size_t)bb * E_ + c) * T_ + tp]       = __float2half_rn(v00);
            g_vt[((size_t)bb * E_ + c + 1) * T_ + tp]   = __float2half_rn(v01);
            g_vt[((size_t)bb * E_ + c) * T_ + tp8]      = __float2half_rn(v10);
            g_vt[((size_t)bb * E_ + c + 1) * T_ + tp8]  = __float2half_rn(v11);
        }
    }
}

// ---------------------------------------------------------------------------
// Kernel 1.5: K' fold (positionwise -> permutation preserved). grid (64, 2).
// ---------------------------------------------------------------------------
__global__ __launch_bounds__(256) void kprep(const float* __restrict__ w1)
{
    __shared__ __align__(16) __half Ksm[8 * 768];
    __shared__ float w1s[1152];
    const int b  = blockIdx.y;
    const int t0 = blockIdx.x * 8;
    const int tid = threadIdx.x;
    const float inv_scale = 0.03608439182435161f;  // 1/sqrt(768)

    #pragma unroll
    for (int i = 0; i < 3; i++) {          // 768 uint4 of K tile
        int idx = tid + i * 256;
        int r = idx / 96, cu = (idx % 96) * 8;
        *(uint4*)&Ksm[r * 768 + cu] =
            *(const uint4*)&g_kh[(size_t)(b * T_ + t0 + r) * E_ + cu];
    }
    for (int idx = tid; idx < 1152; idx += 256) w1s[idx] = w1[idx] * inv_scale;
    __syncthreads();

    const int t = tid >> 5;       // 0..7 key row
    const int i = tid & 31;       // half2 position within 64-block
    float2 kf[12];
    #pragma unroll
    for (int kh = 0; kh < 12; kh++)
        kf[kh] = __half22float2(*(const __half2*)&Ksm[t * 768 + kh * 64 + 2 * i]);

    __half2* outp = (__half2*)g_kph;
    const size_t base = ((size_t)b * H_ * T_ + (size_t)(t0 + t)) * 8;  // row units
    #pragma unroll 4
    for (int go = 0; go < 96; go++) {
        float ax = 0.f, ay = 0.f;
        #pragma unroll
        for (int kh = 0; kh < 12; kh++) {
            float w = w1s[go * 12 + kh];
            ax = fmaf(w, kf[kh].x, ax);
            ay = fmaf(w, kf[kh].y, ay);
        }
        const int g = go >> 3, o = go & 7;
        outp[(base + (size_t)g * T_ * 8 + o) * 32 + i] = __floats2half2_rn(ax, ay);
    }
}

// ---------------------------------------------------------------------------
// Kernel 2: fused hidden(fp16 mma) -> MLP tail -> ctx(fp16 mma).
// grid (16, 12, 2), 256 threads (8 warps = 2 lb x 4 wn). Q in registers.
// ---------------------------------------------------------------------------
#define TK 16
#define LT 32
// smem halves: Ks 128 rows x 96 (192B rows, bank-safe), VsT 2x(64x16), Ws 32x16
#define VS_OFF 12288
#define WS_OFF 14336
#define SMEM_HALVES 14848

__global__ __launch_bounds__(256, 3) void attn_fused(
    const float* __restrict__ b1, const float* __restrict__ w2,
    const float* __restrict__ b2, const float* __restrict__ w3,
    const float* __restrict__ b3, const float* __restrict__ w4,
    const float* __restrict__ b4, float* __restrict__ out)
{
    __shared__ __align__(16) __half smh[SMEM_HALVES];
    __half* Ks  = smh;
    __half* VsT = smh + VS_OFF;
    __half* Ws  = smh + WS_OFF;

    const int b  = blockIdx.z;
    const int g  = blockIdx.y;
    const int l0 = blockIdx.x * LT;
    const int tid  = threadIdx.x;
    const int lane = tid & 31;
    const int warp = tid >> 5;
    const int gid  = lane >> 2;
    const int tig  = lane & 3;
    const int lb   = warp >> 2;   // 0..1
    const int wn   = warp & 3;    // 0..3

    const float b1lo = __ldg(&b1[g * 8 + 2 * tig]);
    const float b1hi = __ldg(&b1[g * 8 + 2 * tig + 1]);
    const float w2lo = __ldg(&w2[g * 8 + 2 * tig]);
    const float w2hi = __ldg(&w2[g * 8 + 2 * tig + 1]);
    const float b2r = __ldg(&b2[g]), b4r = __ldg(&b4[g]);
    float w3r[4], b3r[4], w4r[4];
    #pragma unroll
    for (int j = 0; j < 4; j++) {
        w3r[j] = __ldg(&w3[g * 4 + j]);
        b3r[j] = __ldg(&b3[g * 4 + j]);
        w4r[j] = __ldg(&w4[g * 4 + j]);
    }

    const int row0 = b * T_ + l0 + lb * 16 + gid;

    // Q fragments, loop-invariant: 2 chunk-pairs x 2 rows x 16B = 16 regs
    uint4 qa[2], qb[2];
    {
        const __half* q0 = g_qh + (size_t)row0 * E_ + g * 64;
        const __half* q1 = g_qh + (size_t)(row0 + 8) * E_ + g * 64;
        #pragma unroll
        for (int p = 0; p < 2; p++) {
            qa[p] = *(const uint4*)(q0 + p * 32 + tig * 8);
            qb[p] = *(const uint4*)(q1 + p * 32 + tig * 8);
        }
    }

    const __half* Kg = g_kph + (size_t)(b * H_ + g) * (T_ * 8 * HD_);
    const unsigned ks_s = smem_u32(Ks);
    const unsigned vs_s = smem_u32(VsT);

    auto stage = [&](int tile) {
        const __half* kt = Kg + (size_t)tile * (TK * 8 * HD_);
        #pragma unroll
        for (int i = 0; i < 4; i++) {
            int idx = tid + i * 256;                 // 1024 slots of 16B
            int r = idx >> 3, s = idx & 7;
            cp_async16(ks_s + (unsigned)(r * 192 + s * 16), kt + (size_t)idx * 8);
        }
        if (tid < 128) {                              // V: 64 d-rows x 32B
            int r = tid >> 1, s = tid & 1;
            cp_async16(vs_s + (unsigned)((tile & 1) * 2048 + r * 32 + s * 16),
                       g_vt + ((size_t)(b * E_ + g * 64 + r)) * T_ + tile * TK + s * 8);
        }
        cp_commit();
    };

    stage(0);
    cp_wait_all();
    __syncthreads();

    float cacc[2][4] = {};

    for (int ti = 0; ti < T_ / TK; ti++) {
        const bool more = (ti + 1) < (T_ / TK);

        // ---- hidden = b1 + Q.K' (fp16 mma over n=(t-row: 8 o)) ----
        float d[4][4];
        #pragma unroll
        for (int nb = 0; nb < 4; nb++) {
            d[nb][0] = b1lo; d[nb][1] = b1hi; d[nb][2] = b1lo; d[nb][3] = b1hi;
        }
        #pragma unroll
        for (int nb = 0; nb < 4; nb++) {
            const int t = wn * 4 + nb;
            const __half* kr = Ks + (t * 8 + gid) * 96 + tig * 8;
            #pragma unroll
            for (int p = 0; p < 2; p++) {
                uint4 kb = *(const uint4*)(kr + p * 32);
                mma_f16(d[nb][0], d[nb][1], d[nb][2], d[nb][3],
                        qa[p].x, qb[p].x, qa[p].y, qb[p].y, kb.x, kb.y);
                mma_f16(d[nb][0], d[nb][1], d[nb][2], d[nb][3],
                        qa[p].z, qb[p].z, qa[p].w, qb[p].w, kb.z, kb.w);
            }
        }

        // ---- MLP tail: relu -> w2 (quad reduce) -> relu(4) -> w4 ----
        #pragma unroll
        for (int nb = 0; nb < 4; nb++) {
            const int t = wn * 4 + nb;
            float u0 = fmaf(w2lo, fmaxf(d[nb][0], 0.f), w2hi * fmaxf(d[nb][1], 0.f));
            float u1 = fmaf(w2lo, fmaxf(d[nb][2], 0.f), w2hi * fmaxf(d[nb][3], 0.f));
            u0 += __shfl_xor_sync(0xffffffff, u0, 1);
            u0 += __shfl_xor_sync(0xffffffff, u0, 2);
            u1 += __shfl_xor_sync(0xffffffff, u1, 1);
            u1 += __shfl_xor_sync(0xffffffff, u1, 2);
            float a20 = u0 + b2r, a21 = u1 + b2r;
            float wv0 = b4r, wv1 = b4r;
            #pragma unroll
            for (int j = 0; j < 4; j++) {
                wv0 = fmaf(w4r[j], fmaxf(fmaf(w3r[j], a20, b3r[j]), 0.f), wv0);
                wv1 = fmaf(w4r[j], fmaxf(fmaf(w3r[j], a21, b3r[j]), 0.f), wv1);
            }
            if (tig == 0) {
                const int st = s16(t);
                Ws[(lb * 16 + gid) * 16 + st]     = __float2half_rn(wv0);
                Ws[(lb * 16 + gid + 8) * 16 + st] = __float2half_rn(wv1);
            }
        }
        __syncthreads();   // Ws visible; scores done with Ks

        if (more) stage(ti + 1);

        // ---- ctx: cacc += Ws[32,16] @ V[16,64]  (one k16 chunk) ----
        {
            uint2 wa = *(const uint2*)&Ws[(lb * 16 + gid) * 16 + tig * 4];
            uint2 wbv = *(const uint2*)&Ws[(lb * 16 + gid + 8) * 16 + tig * 4];
            const __half* Vb = VsT + (ti & 1) * 1024;
            #pragma unroll
            for (int nd = 0; nd < 2; nd++) {
                const int dr = wn * 16 + nd * 8 + gid;
                uint2 vb = *(const uint2*)&Vb[dr * 16 + tig * 4];
                mma_f16(cacc[nd][0], cacc[nd][1], cacc[nd][2], cacc[nd][3],
                        wa.x, wbv.x, wa.y, wbv.y, vb.x, vb.y);
            }
        }

        if (more) cp_wait_all();
        __syncthreads();
    }

    #pragma unroll
    for (int nd = 0; nd < 2; nd++) {
        const int col = g * 64 + wn * 16 + nd * 8 + 2 * tig;
        *(float2*)&out[(size_t)row0 * E_ + col] =
            make_float2(cacc[nd][0], cacc[nd][1]);
        *(float2*)&out[(size_t)(row0 + 8) * E_ + col] =
            make_float2(cacc[nd][2], cacc[nd][3]);
    }
}

// ---------------------------------------------------------------------------
extern "C" void kernel_launch(void* const* d_in, const int* in_sizes, int n_in,
                              void* d_out, int out_size)
{
    const float* x  = (const float*)d_in[0];
    const float* wq = (const float*)d_in[1];
    const float* bq = (const float*)d_in[2];
    const float* wk = (const float*)d_in[3];
    const float* bk = (const float*)d_in[4];
    const float* wv = (const float*)d_in[5];
    const float* bv = (const float*)d_in[6];
    const float* w1 = (const float*)d_in[7];
    const float* b1 = (const float*)d_in[8];
    const float* w2 = (const float*)d_in[9];
    const float* b2 = (const float*)d_in[10];
    const float* w3 = (const float*)d_in[11];
    const float* b3 = (const float*)d_in[12];
    const float* w4 = (const float*)d_in[13];
    const float* b4 = (const float*)d_in[14];
    float* out = (float*)d_out;

    dim3 pgrid(B_ * T_, 4);
    prep<<<pgrid, 192>>>(x, wq, wk, wv);

    dim3 ggrid(E_ / 64, (B_ * T_) / 64, 3);
    qkv_mma<<<ggrid, 256>>>(bq, bk, bv);

    dim3 kgrid(T_ / 8, B_);
    kprep<<<kgrid, 256>>>(w1);

    dim3 agrid(T_ / LT, H_, B_);
    attn_fused<<<agrid, 256>>>(b1, w2, b2, w3, b3, w4, b4, out);
}

// round 7
// speedup vs baseline: 8.2934x; 1.1821x over previous
#include <cuda_runtime.h>
#include <cuda_fp16.h>

#define B_  2
#define T_  512
#define E_  768
#define H_  12
#define HD_ 64

__device__ __half g_xh[B_ * T_ * E_];
__device__ __half g_wh[3 * E_ * E_];
__device__ __half g_qh[B_ * T_ * E_];
__device__ __half g_kh[B_ * T_ * E_];
__device__ __half g_vt[B_ * E_ * T_];
__device__ __half g_kph[B_ * H_ * T_ * 8 * HD_];

// slot of k within a 16-chunk for fp16 mma fragments
__device__ __forceinline__ int s16(int k) {
    return 4 * ((k >> 1) & 3) + 2 * ((k >> 3) & 1) + (k & 1);
}
// position of k within a 64-block: chunk-pairs of 32, thread-slot interleaved
__device__ __forceinline__ int hperm64(int w) {
    int p = w >> 5, c1 = (w >> 4) & 1, k0 = w & 15;
    return p * 32 + ((k0 >> 1) & 3) * 8 + c1 * 4 + ((k0 >> 3) & 1) * 2 + (k0 & 1);
}

__device__ __forceinline__ void mma_f16(
    float& d0, float& d1, float& d2, float& d3,
    unsigned a0, unsigned a1, unsigned a2, unsigned a3,
    unsigned b0, unsigned b1)
{
    asm volatile(
        "mma.sync.aligned.m16n8k16.row.col.f32.f16.f16.f32 "
        "{%0,%1,%2,%3}, {%4,%5,%6,%7}, {%8,%9}, {%0,%1,%2,%3};"
        : "+f"(d0), "+f"(d1), "+f"(d2), "+f"(d3)
        : "r"(a0), "r"(a1), "r"(a2), "r"(a3), "r"(b0), "r"(b1));
}

__device__ __forceinline__ unsigned smem_u32(const void* p) {
    return (unsigned)__cvta_generic_to_shared(p);
}
__device__ __forceinline__ void cp_async16(unsigned s, const void* g) {
    asm volatile("cp.async.cg.shared.global [%0], [%1], 16;" :: "r"(s), "l"(g));
}
__device__ __forceinline__ void cp_commit()   { asm volatile("cp.async.commit_group;"); }
__device__ __forceinline__ void cp_wait1()    { asm volatile("cp.async.wait_group 1;"); }
__device__ __forceinline__ void cp_wait_all() { asm volatile("cp.async.wait_group 0;"); }

// ---------------------------------------------------------------------------
// Kernel 0: fp32 -> fp16 with k-permutation.
// ---------------------------------------------------------------------------
__global__ __launch_bounds__(192) void prep(
    const float* __restrict__ x,  const float* __restrict__ wq,
    const float* __restrict__ wk, const float* __restrict__ wv)
{
    const int z = blockIdx.y;
    const float* src; __half* dst; int nrows;
    if (z == 0)      { src = x;  dst = g_xh;               nrows = B_ * T_; }
    else if (z == 1) { src = wq; dst = g_wh;               nrows = E_; }
    else if (z == 2) { src = wk; dst = g_wh + E_ * E_;     nrows = E_; }
    else             { src = wv; dst = g_wh + 2 * E_ * E_; nrows = E_; }
    const int row = blockIdx.x;
    if (row >= nrows) return;
    const int c0 = threadIdx.x * 4;
    float4 v = *(const float4*)&src[(size_t)row * E_ + c0];
    const int blk = (c0 >> 6) * 64, w = c0 & 63;
    __half* d = dst + (size_t)row * E_;
    *(__half2*)&d[blk + hperm64(w)]     = __floats2half2_rn(v.x, v.y);
    *(__half2*)&d[blk + hperm64(w + 2)] = __floats2half2_rn(v.z, v.w);
}

// ---------------------------------------------------------------------------
// Kernel 1: QKV projection, fp16 mma, 2-stage cp.async pipeline.
// ---------------------------------------------------------------------------
__global__ __launch_bounds__(256) void qkv_mma(
    const float* __restrict__ bq, const float* __restrict__ bk,
    const float* __restrict__ bv)
{
    __shared__ __align__(16) __half sh[8192];
    const int z = blockIdx.z;
    const __half* Wg = g_wh + (size_t)z * E_ * E_;
    const float* bias = (z == 0) ? bq : (z == 1) ? bk : bv;

    const int tid  = threadIdx.x;
    const int lane = tid & 31;
    const int warp = tid >> 5;
    const int gid  = lane >> 2;
    const int tig  = lane & 3;
    const int mw   = warp & 3;
    const int nw   = warp >> 2;
    const int m0 = blockIdx.y * 64;
    const int n0 = blockIdx.x * 64;

    const unsigned sh_s = smem_u32(sh);
    const int srow = tid & 63;
    const int sslot = tid >> 6;

    auto stage = [&](int it) {
        const int buf = it & 1;
        const int k0 = it * 32;
        const int swz = (sslot ^ (srow & 3)) * 16;
        cp_async16(sh_s + (unsigned)((buf * 2048 + srow * 32) * 2 + swz),
                   g_xh + (size_t)(m0 + srow) * E_ + k0 + sslot * 8);
        cp_async16(sh_s + (unsigned)((4096 + buf * 2048 + srow * 32) * 2 + swz),
                   Wg + (size_t)(n0 + srow) * E_ + k0 + sslot * 8);
        cp_commit();
    };

    float acc[4][4];
    #pragma unroll
    for (int nb = 0; nb < 4; nb++)
        #pragma unroll
        for (int i = 0; i < 4; i++) acc[nb][i] = 0.f;

    stage(0);
    stage(1);

    for (int it = 0; it < 24; it++) {
        if (it == 23) cp_wait_all(); else cp_wait1();
        __syncthreads();
        const __half* Xb = sh + (it & 1) * 2048;
        const __half* Wb = sh + 4096 + (it & 1) * 2048;
        const int m = mw * 16 + gid, m8 = m + 8;
        uint4 xa = *(const uint4*)(Xb + m * 32 + ((tig ^ (m & 3)) * 8));
        uint4 xb = *(const uint4*)(Xb + m8 * 32 + ((tig ^ (m8 & 3)) * 8));
        #pragma unroll
        for (int nb = 0; nb < 4; nb++) {
            const int n = nw * 32 + nb * 8 + gid;
            uint4 wb = *(const uint4*)(Wb + n * 32 + ((tig ^ (n & 3)) * 8));
            mma_f16(acc[nb][0], acc[nb][1], acc[nb][2], acc[nb][3],
                    xa.x, xb.x, xa.y, xb.y, wb.x, wb.y);
            mma_f16(acc[nb][0], acc[nb][1], acc[nb][2], acc[nb][3],
                    xa.z, xb.z, xa.w, xb.w, wb.z, wb.w);
        }
        __syncthreads();
        if (it + 2 < 24) stage(it + 2);
    }

    #pragma unroll
    for (int nb = 0; nb < 4; nb++) {
        const int c = n0 + nw * 32 + nb * 8 + 2 * tig;
        const float bz0 = bias[c], bz1 = bias[c + 1];
        const int r0 = m0 + mw * 16 + gid;
        float v00 = acc[nb][0] + bz0, v01 = acc[nb][1] + bz1;
        float v10 = acc[nb][2] + bz0, v11 = acc[nb][3] + bz1;
        if (z < 2) {
            __half* o = z ? g_kh : g_qh;
            const int pos = (c & ~63) + hperm64(c & 63);
            *(__half2*)&o[(size_t)r0 * E_ + pos]       = __floats2half2_rn(v00, v01);
            *(__half2*)&o[(size_t)(r0 + 8) * E_ + pos] = __floats2half2_rn(v10, v11);
        } else {
            const int bb = r0 >> 9;
            const int t  = r0 & 511, t8 = (r0 + 8) & 511;
            const int tp  = (t & ~15) | s16(t & 15);
            const int tp8 = (t8 & ~15) | s16(t8 & 15);
            g_vt[((size_t)bb * E_ + c) * T_ + tp]       = __float2half_rn(v00);
            g_vt[((size_t)bb * E_ + c + 1) * T_ + tp]   = __float2half_rn(v01);
            g_vt[((size_t)bb * E_ + c) * T_ + tp8]      = __float2half_rn(v10);
            g_vt[((size_t)bb * E_ + c + 1) * T_ + tp8]  = __float2half_rn(v11);
        }
    }
}

// ---------------------------------------------------------------------------
// Kernel 1.5: K' fold.
// ---------------------------------------------------------------------------
__global__ __launch_bounds__(256) void kprep(const float* __restrict__ w1)
{
    __shared__ __align__(16) __half Ksm[8 * 768];
    __shared__ float w1s[1152];
    const int b  = blockIdx.y;
    const int t0 = blockIdx.x * 8;
    const int tid = threadIdx.x;
    const float inv_scale = 0.03608439182435161f;

    #pragma unroll
    for (int i = 0; i < 3; i++) {
        int idx = tid + i * 256;
        int r = idx / 96, cu = (idx % 96) * 8;
        *(uint4*)&Ksm[r * 768 + cu] =
            *(const uint4*)&g_kh[(size_t)(b * T_ + t0 + r) * E_ + cu];
    }
    for (int idx = tid; idx < 1152; idx += 256) w1s[idx] = w1[idx] * inv_scale;
    __syncthreads();

    const int t = tid >> 5;
    const int i = tid & 31;
    float2 kf[12];
    #pragma unroll
    for (int kh = 0; kh < 12; kh++)
        kf[kh] = __half22float2(*(const __half2*)&Ksm[t * 768 + kh * 64 + 2 * i]);

    __half2* outp = (__half2*)g_kph;
    const size_t base = ((size_t)b * H_ * T_ + (size_t)(t0 + t)) * 8;
    #pragma unroll 4
    for (int go = 0; go < 96; go++) {
        float ax = 0.f, ay = 0.f;
        #pragma unroll
        for (int kh = 0; kh < 12; kh++) {
            float w = w1s[go * 12 + kh];
            ax = fmaf(w, kf[kh].x, ax);
            ay = fmaf(w, kf[kh].y, ay);
        }
        const int g = go >> 3, o = go & 7;
        outp[(base + (size_t)g * T_ * 8 + o) * 32 + i] = __floats2half2_rn(ax, ay);
    }
}

// ---------------------------------------------------------------------------
// Kernel 2: fused hidden(fp16 mma) -> MLP tail (reduce-scatter) -> ctx(mma).
// grid (16, 12, 2), 256 threads. TK=32, swizzled Ks, two 16-key phases/tile.
// ---------------------------------------------------------------------------
#define TK 32
#define LT 32
#define KS_HALVES 16384            // 256 rows x 64 halves, XOR-swizzled
#define VS_HALVES 4096             // 2 buf x 2 chunks x (64 x 16)
#define WS_HALVES 1536             // 32 rows x 48 (pad)

__global__ __launch_bounds__(256, 3) void attn_fused(
    const float* __restrict__ b1, const float* __restrict__ w2,
    const float* __restrict__ b2, const float* __restrict__ w3,
    const float* __restrict__ b3, const float* __restrict__ w4,
    const float* __restrict__ b4, float* __restrict__ out)
{
    __shared__ __align__(16) __half Ks[KS_HALVES];
    __shared__ __align__(16) __half VsT[VS_HALVES];
    __shared__ __align__(16) __half Ws[WS_HALVES];

    const int b  = blockIdx.z;
    const int g  = blockIdx.y;
    const int l0 = blockIdx.x * LT;
    const int tid  = threadIdx.x;
    const int lane = tid & 31;
    const int warp = tid >> 5;
    const int gid  = lane >> 2;
    const int tig  = lane & 3;
    const int lb   = warp >> 2;   // 0..1
    const int wn   = warp & 3;    // 0..3

    const float b1lo = __ldg(&b1[g * 8 + 2 * tig]);
    const float b1hi = __ldg(&b1[g * 8 + 2 * tig + 1]);
    const float w2lo = __ldg(&w2[g * 8 + 2 * tig]);
    const float w2hi = __ldg(&w2[g * 8 + 2 * tig + 1]);
    const float b2r = __ldg(&b2[g]), b4r = __ldg(&b4[g]);
    float w3r[4], b3r[4], w4r[4];
    #pragma unroll
    for (int j = 0; j < 4; j++) {
        w3r[j] = __ldg(&w3[g * 4 + j]);
        b3r[j] = __ldg(&b3[g * 4 + j]);
        w4r[j] = __ldg(&w4[g * 4 + j]);
    }

    const int row0 = b * T_ + l0 + lb * 16 + gid;

    // Q fragments, loop-invariant
    uint4 qa[2], qb[2];
    {
        const __half* q0 = g_qh + (size_t)row0 * E_ + g * 64;
        const __half* q1 = g_qh + (size_t)(row0 + 8) * E_ + g * 64;
        #pragma unroll
        for (int p = 0; p < 2; p++) {
            qa[p] = *(const uint4*)(q0 + p * 32 + tig * 8);
            qb[p] = *(const uint4*)(q1 + p * 32 + tig * 8);
        }
    }

    const __half* Kg = g_kph + (size_t)(b * H_ + g) * (T_ * 8 * HD_);
    const unsigned ks_s = smem_u32(Ks);
    const unsigned vs_s = smem_u32(VsT);

    auto stage = [&](int tile) {
        const __half* kt = Kg + (size_t)tile * (TK * 8 * HD_);
        #pragma unroll
        for (int i = 0; i < 8; i++) {
            int idx = tid + i * 256;              // 2048 x 16B chunks
            int r = idx >> 3, c = idx & 7;
            int cs = c ^ (4 * (r & 1));           // XOR swizzle
            cp_async16(ks_s + (unsigned)(r * 128 + cs * 16), kt + (size_t)idx * 8);
        }
        // V: 2 k16 chunks, each 64 rows x 16 halves
        {
            int kc = tid >> 7, r = (tid >> 1) & 63, s = tid & 1;
            cp_async16(vs_s + (unsigned)(((tile & 1) * 2048 + kc * 1024 + r * 16 + s * 8) * 2),
                       g_vt + ((size_t)(b * E_ + g * 64 + r)) * T_ + tile * TK + kc * 16 + s * 8);
        }
        cp_commit();
    };

    stage(0);
    cp_wait_all();
    __syncthreads();

    float cacc[2][4] = {};
    const int kboff = tig * 8 + (gid & 1) * 32;     // swizzled frag offset (halves)
    const int st = s16(wn * 4 + tig);               // Ws col slot for this thread's t
    const bool lo1 = (tig & 1) == 0;
    const bool lo2 = (tig & 2) == 0;
    __half* ws_w0 = Ws + (lb * 16 + gid) * 48 + st;
    __half* ws_w1 = ws_w0 + 8 * 48;

    for (int ti = 0; ti < T_ / TK; ti++) {
        const bool more = (ti + 1) < (T_ / TK);

        #pragma unroll
        for (int ph = 0; ph < 2; ph++) {
            // ---- hidden = b1 + Q.K' ----
            float d[4][4];
            #pragma unroll
            for (int nb = 0; nb < 4; nb++) {
                d[nb][0] = b1lo; d[nb][1] = b1hi; d[nb][2] = b1lo; d[nb][3] = b1hi;
            }
            #pragma unroll
            for (int nb = 0; nb < 4; nb++) {
                const __half* kr = Ks + (((ph * 16 + wn * 4 + nb) * 8) + gid) * 64;
                uint4 kb0 = *(const uint4*)(kr + kboff);
                uint4 kb1 = *(const uint4*)(kr + (kboff ^ 32));
                mma_f16(d[nb][0], d[nb][1], d[nb][2], d[nb][3],
                        qa[0].x, qb[0].x, qa[0].y, qb[0].y, kb0.x, kb0.y);
                mma_f16(d[nb][0], d[nb][1], d[nb][2], d[nb][3],
                        qa[0].z, qb[0].z, qa[0].w, qb[0].w, kb0.z, kb0.w);
                mma_f16(d[nb][0], d[nb][1], d[nb][2], d[nb][3],
                        qa[1].x, qb[1].x, qa[1].y, qb[1].y, kb1.x, kb1.y);
                mma_f16(d[nb][0], d[nb][1], d[nb][2], d[nb][3],
                        qa[1].z, qb[1].z, qa[1].w, qb[1].w, kb1.z, kb1.w);
            }

            // ---- u = w2 . relu(h) partials ----
            float u0[4], u1[4];
            #pragma unroll
            for (int nb = 0; nb < 4; nb++) {
                u0[nb] = fmaf(w2lo, fmaxf(d[nb][0], 0.f), w2hi * fmaxf(d[nb][1], 0.f));
                u1[nb] = fmaf(w2lo, fmaxf(d[nb][2], 0.f), w2hi * fmaxf(d[nb][3], 0.f));
            }

            // ---- quad reduce-scatter: thread tig gets full sum for nb = tig ----
            float a0, a1;
            {
                float k0 = lo1 ? u0[0] : u0[1], s0 = lo1 ? u0[1] : u0[0];
                k0 += __shfl_xor_sync(0xffffffffu, s0, 1);
                float k1 = lo1 ? u0[2] : u0[3], s1 = lo1 ? u0[3] : u0[2];
                k1 += __shfl_xor_sync(0xffffffffu, s1, 1);
                float kk = lo2 ? k0 : k1, ss = lo2 ? k1 : k0;
                a0 = kk + __shfl_xor_sync(0xffffffffu, ss, 2);
            }
            {
                float k0 = lo1 ? u1[0] : u1[1], s0 = lo1 ? u1[1] : u1[0];
                k0 += __shfl_xor_sync(0xffffffffu, s0, 1);
                float k1 = lo1 ? u1[2] : u1[3], s1 = lo1 ? u1[3] : u1[2];
                k1 += __shfl_xor_sync(0xffffffffu, s1, 1);
                float kk = lo2 ? k0 : k1, ss = lo2 ? k1 : k0;
                a1 = kk + __shfl_xor_sync(0xffffffffu, ss, 2);
            }

            // ---- tail once per thread ----
            float a20 = a0 + b2r, a21 = a1 + b2r;
            float wv0 = b4r, wv1 = b4r;
            #pragma unroll
            for (int j = 0; j < 4; j++) {
                wv0 = fmaf(w4r[j], fmaxf(fmaf(w3r[j], a20, b3r[j]), 0.f), wv0);
                wv1 = fmaf(w4r[j], fmaxf(fmaf(w3r[j], a21, b3r[j]), 0.f), wv1);
            }
            ws_w0[ph * 16] = __float2half_rn(wv0);
            ws_w1[ph * 16] = __float2half_rn(wv1);
        }
        __syncthreads();   // Ws complete; scores done with Ks

        if (more) stage(ti + 1);   // Ks overwrite + other V buffer

        // ---- ctx: cacc += Ws[32,32] @ V[32,64] (two k16 chunks) ----
        const __half* Vb = VsT + (ti & 1) * 2048;
        #pragma unroll
        for (int kc = 0; kc < 2; kc++) {
            uint2 wa  = *(const uint2*)&Ws[(lb * 16 + gid) * 48 + kc * 16 + tig * 4];
            uint2 wbv = *(const uint2*)&Ws[(lb * 16 + gid + 8) * 48 + kc * 16 + tig * 4];
            #pragma unroll
            for (int nd = 0; nd < 2; nd++) {
                const int dr = wn * 16 + nd * 8 + gid;
                uint2 vb = *(const uint2*)&Vb[kc * 1024 + dr * 16 + tig * 4];
                mma_f16(cacc[nd][0], cacc[nd][1], cacc[nd][2], cacc[nd][3],
                        wa.x, wbv.x, wa.y, wbv.y, vb.x, vb.y);
            }
        }

        if (more) cp_wait_all();
        __syncthreads();
    }

    #pragma unroll
    for (int nd = 0; nd < 2; nd++) {
        const int col = g * 64 + wn * 16 + nd * 8 + 2 * tig;
        *(float2*)&out[(size_t)row0 * E_ + col] =
            make_float2(cacc[nd][0], cacc[nd][1]);
        *(float2*)&out[(size_t)(row0 + 8) * E_ + col] =
            make_float2(cacc[nd][2], cacc[nd][3]);
    }
}

// ---------------------------------------------------------------------------
extern "C" void kernel_launch(void* const* d_in, const int* in_sizes, int n_in,
                              void* d_out, int out_size)
{
    const float* x  = (const float*)d_in[0];
    const float* wq = (const float*)d_in[1];
    const float* bq = (const float*)d_in[2];
    const float* wk = (const float*)d_in[3];
    const float* bk = (const float*)d_in[4];
    const float* wv = (const float*)d_in[5];
    const float* bv = (const float*)d_in[6];
    const float* w1 = (const float*)d_in[7];
    const float* b1 = (const float*)d_in[8];
    const float* w2 = (const float*)d_in[9];
    const float* b2 = (const float*)d_in[10];
    const float* w3 = (const float*)d_in[11];
    const float* b3 = (const float*)d_in[12];
    const float* w4 = (const float*)d_in[13];
    const float* b4 = (const float*)d_in[14];
    float* out = (float*)d_out;

    dim3 pgrid(B_ * T_, 4);
    prep<<<pgrid, 192>>>(x, wq, wk, wv);

    dim3 ggrid(E_ / 64, (B_ * T_) / 64, 3);
    qkv_mma<<<ggrid, 256>>>(bq, bk, bv);

    dim3 kgrid(T_ / 8, B_);
    kprep<<<kgrid, 256>>>(w1);

    dim3 agrid(T_ / LT, H_, B_);
    attn_fused<<<agrid, 256>>>(b1, w2, b2, w3, b3, w4, b4, out);
}